// round 8
// baseline (speedup 1.0000x reference)
#include <cuda_runtime.h>
#include <cuda_bf16.h>
#include <cstdint>

// Problem constants
#define BB 4
#define SS 2048
#define DD 1024
#define HH 16
#define HDIM 64
#define MM (BB * SS)   // 8192

// ---------------------------------------------------------------------------
// Static device scratch (no runtime allocation allowed)
// ---------------------------------------------------------------------------
__device__ float g_q[MM * DD];
__device__ float g_k[MM * DD];
__device__ float g_v[MM * DD];
__device__ float g_ctx[MM * DD];

__device__ __nv_bfloat16 g_xh[MM * DD];
__device__ __nv_bfloat16 g_xl[MM * DD];
__device__ __nv_bfloat16 g_ch[MM * DD];
__device__ __nv_bfloat16 g_cl[MM * DD];
__device__ __nv_bfloat16 g_wh[4][DD * DD];  // transposed W hi: [N][K]
__device__ __nv_bfloat16 g_wl[4][DD * DD];  // transposed W lo: [N][K]

// ---------------------------------------------------------------------------
// PTX helpers (arch-agnostic: cp.async + ldmatrix + mma.sync only)
// ---------------------------------------------------------------------------
__device__ __forceinline__ uint32_t smem_u32(const void* p) {
    return (uint32_t)__cvta_generic_to_shared(p);
}

__device__ __forceinline__ void cp16(uint32_t dst, const void* src) {
    asm volatile("cp.async.cg.shared.global [%0], [%1], 16;" :: "r"(dst), "l"(src));
}

__device__ __forceinline__ void ldsm4(uint32_t& r0, uint32_t& r1, uint32_t& r2,
                                      uint32_t& r3, uint32_t addr) {
    asm volatile("ldmatrix.sync.aligned.m8n8.x4.shared.b16 {%0,%1,%2,%3}, [%4];"
                 : "=r"(r0), "=r"(r1), "=r"(r2), "=r"(r3) : "r"(addr));
}

__device__ __forceinline__ void mma_bf16(float c[4], uint32_t a0, uint32_t a1,
                                         uint32_t a2, uint32_t a3,
                                         uint32_t b0, uint32_t b1) {
    asm volatile(
        "mma.sync.aligned.m16n8k16.row.col.f32.bf16.bf16.f32 "
        "{%0,%1,%2,%3}, {%4,%5,%6,%7}, {%8,%9}, {%0,%1,%2,%3};"
        : "+f"(c[0]), "+f"(c[1]), "+f"(c[2]), "+f"(c[3])
        : "r"(a0), "r"(a1), "r"(a2), "r"(a3), "r"(b0), "r"(b1));
}

// ---------------------------------------------------------------------------
// bf16-split HMMA GEMM: C[M,1024] = A[M,1024] @ W^T[N=1024,K] (+bias)
//   A hi/lo bf16 row-major [M,K]; W hi/lo TRANSPOSED [N,K] row-major.
//   C = Ah*Bh + Ah*Bl + Al*Bh, fp32 accumulate in registers.
// CTA tile 128x128, 8 warps (4m x 2n), warp tile 32x64 via m16n8k16.
// K-chunks of 32, double-buffered cp.async.
// ---------------------------------------------------------------------------
#define KC 32
#define ASTRIDE 40                    // bf16 elems per smem row (80B, conflict-free)
#define OP_ELEMS (128 * ASTRIDE)      // per operand per stage
#define NSTG 2
#define NCHUNK 96                     // 3 passes * (1024/32)
#define GEMM_SMEM (NSTG * 2 * OP_ELEMS * 2)  // 40960 bytes

template <bool BIAS>
__global__ __launch_bounds__(256, 2)
void gemm_mma(const __nv_bfloat16* __restrict__ Ah, const __nv_bfloat16* __restrict__ Al,
              const __nv_bfloat16* __restrict__ Bh, const __nv_bfloat16* __restrict__ Bl,
              const float* __restrict__ bias, float* __restrict__ C) {
    extern __shared__ __align__(16) char dyn_smem[];
    __nv_bfloat16* sm = (__nv_bfloat16*)dyn_smem;

    const int tid = threadIdx.x;
    const int wid = tid >> 5;
    const int lane = tid & 31;
    const int wm = (wid & 3) * 32;        // warp m offset within tile
    const int wn = (wid >> 2) * 64;       // warp n offset within tile
    const int m0 = blockIdx.y * 128;
    const int n0 = blockIdx.x * 128;

    float acc[2][8][4];
#pragma unroll
    for (int i = 0; i < 2; i++)
#pragma unroll
        for (int j = 0; j < 8; j++)
#pragma unroll
            for (int t = 0; t < 4; t++) acc[i][j][t] = 0.f;

    // Per-thread load geometry: 2 segments per operand (512 x 16B per operand)
    const int seg0 = tid, seg1 = tid + 256;
    const int r0 = seg0 >> 2, c0 = (seg0 & 3) * 8;
    const int r1 = seg1 >> 2, c1 = (seg1 & 3) * 8;

    auto load_chunk = [&](int c) {
        const int p = c >> 5;          // 0: Ah*Bh, 1: Ah*Bl, 2: Al*Bh
        const int koff = (c & 31) * KC;
        const __nv_bfloat16* Asrc = (p < 2) ? Ah : Al;
        const __nv_bfloat16* Bsrc = (p == 1) ? Bl : Bh;
        __nv_bfloat16* sa = sm + (c & (NSTG - 1)) * 2 * OP_ELEMS;
        __nv_bfloat16* sb = sa + OP_ELEMS;
        cp16(smem_u32(sa + r0 * ASTRIDE + c0), Asrc + (size_t)(m0 + r0) * DD + koff + c0);
        cp16(smem_u32(sa + r1 * ASTRIDE + c1), Asrc + (size_t)(m0 + r1) * DD + koff + c1);
        cp16(smem_u32(sb + r0 * ASTRIDE + c0), Bsrc + (size_t)(n0 + r0) * DD + koff + c0);
        cp16(smem_u32(sb + r1 * ASTRIDE + c1), Bsrc + (size_t)(n0 + r1) * DD + koff + c1);
        asm volatile("cp.async.commit_group;" ::: "memory");
    };

    // ldmatrix lane address components
    const int a_row = lane & 15;            // row within 16-row A tile
    const int a_col = (lane >> 4) * 8;      // k half
    const int b_row = (lane & 7) + ((lane >> 4) << 3);  // n within 16-row pair
    const int b_col = ((lane >> 3) & 1) * 8;            // k half

    load_chunk(0);

    for (int c = 0; c < NCHUNK; c++) {
        if (c + 1 < NCHUNK) {
            load_chunk(c + 1);
            asm volatile("cp.async.wait_group 1;" ::: "memory");
        } else {
            asm volatile("cp.async.wait_group 0;" ::: "memory");
        }
        __syncthreads();

        const __nv_bfloat16* sa = sm + (c & (NSTG - 1)) * 2 * OP_ELEMS;
        const __nv_bfloat16* sb = sa + OP_ELEMS;

#pragma unroll
        for (int ks = 0; ks < 2; ks++) {   // two k16 steps per chunk
            const int k = ks * 16;
            uint32_t a[2][4];
#pragma unroll
            for (int mt = 0; mt < 2; mt++) {
                uint32_t addr = smem_u32(sa + (wm + mt * 16 + a_row) * ASTRIDE + k + a_col);
                ldsm4(a[mt][0], a[mt][1], a[mt][2], a[mt][3], addr);
            }
            uint32_t b[8][2];
#pragma unroll
            for (int np = 0; np < 4; np++) {  // pairs of n8 tiles
                uint32_t addr = smem_u32(sb + (wn + np * 16 + b_row) * ASTRIDE + k + b_col);
                ldsm4(b[2 * np][0], b[2 * np][1], b[2 * np + 1][0], b[2 * np + 1][1], addr);
            }
#pragma unroll
            for (int mt = 0; mt < 2; mt++)
#pragma unroll
                for (int nt = 0; nt < 8; nt++)
                    mma_bf16(acc[mt][nt], a[mt][0], a[mt][1], a[mt][2], a[mt][3],
                             b[nt][0], b[nt][1]);
        }
        __syncthreads();
    }

    // Epilogue: each mma tile: rows lane/4 and lane/4+8, cols 2*(lane%4)+{0,1}
    const int erow = lane >> 2;
    const int ecol = (lane & 3) * 2;
#pragma unroll
    for (int mt = 0; mt < 2; mt++) {
        const int row = m0 + wm + mt * 16 + erow;
#pragma unroll
        for (int nt = 0; nt < 8; nt++) {
            const int col = n0 + wn + nt * 8 + ecol;
            float2 v0, v1;
            v0.x = acc[mt][nt][0]; v0.y = acc[mt][nt][1];
            v1.x = acc[mt][nt][2]; v1.y = acc[mt][nt][3];
            if (BIAS) {
                v0.x += bias[col]; v0.y += bias[col + 1];
                v1.x += bias[col]; v1.y += bias[col + 1];
            }
            *(float2*)&C[(size_t)row * DD + col] = v0;
            *(float2*)&C[(size_t)(row + 8) * DD + col] = v1;
        }
    }
}

// ---------------------------------------------------------------------------
// Prep kernels: fp32 -> (hi, lo) bf16 split; W transpose+split.
// ---------------------------------------------------------------------------
__global__ __launch_bounds__(256)
void cvt_split_kernel(const float* __restrict__ in, __nv_bfloat16* __restrict__ hi,
                      __nv_bfloat16* __restrict__ lo, int n4) {
    int i = blockIdx.x * blockDim.x + threadIdx.x;
    if (i >= n4) return;
    float4 v = ((const float4*)in)[i];
    __nv_bfloat16 h0 = __float2bfloat16(v.x);
    __nv_bfloat16 h1 = __float2bfloat16(v.y);
    __nv_bfloat16 h2 = __float2bfloat16(v.z);
    __nv_bfloat16 h3 = __float2bfloat16(v.w);
    __nv_bfloat162 hp0; hp0.x = h0; hp0.y = h1;
    __nv_bfloat162 hp1; hp1.x = h2; hp1.y = h3;
    __nv_bfloat162 lp0, lp1;
    lp0.x = __float2bfloat16(v.x - __bfloat162float(h0));
    lp0.y = __float2bfloat16(v.y - __bfloat162float(h1));
    lp1.x = __float2bfloat16(v.z - __bfloat162float(h2));
    lp1.y = __float2bfloat16(v.w - __bfloat162float(h3));
    ((__nv_bfloat162*)hi)[2 * i + 0] = hp0;
    ((__nv_bfloat162*)hi)[2 * i + 1] = hp1;
    ((__nv_bfloat162*)lo)[2 * i + 0] = lp0;
    ((__nv_bfloat162*)lo)[2 * i + 1] = lp1;
}

__global__ __launch_bounds__(256)
void wsplit_t_kernel(const float* __restrict__ W, __nv_bfloat16* __restrict__ Th,
                     __nv_bfloat16* __restrict__ Tl) {
    __shared__ float t[32][33];
    const int bx = blockIdx.x * 32;
    const int by = blockIdx.y * 32;
    const int x = bx + threadIdx.x;
#pragma unroll
    for (int j = threadIdx.y; j < 32; j += 8)
        t[j][threadIdx.x] = W[(size_t)(by + j) * DD + x];
    __syncthreads();
    const int xo = by + threadIdx.x;
#pragma unroll
    for (int j = threadIdx.y; j < 32; j += 8) {
        float v = t[threadIdx.x][j];
        __nv_bfloat16 h = __float2bfloat16(v);
        Th[(size_t)(bx + j) * DD + xo] = h;
        Tl[(size_t)(bx + j) * DD + xo] = __float2bfloat16(v - __bfloat162float(h));
    }
}

// ---------------------------------------------------------------------------
// Flash-attention (fp32) — unchanged from the passing baseline.
// ---------------------------------------------------------------------------
__global__ __launch_bounds__(256)
void attn_kernel(const float* __restrict__ Qg, const float* __restrict__ Kg,
                 const float* __restrict__ Vg, float* __restrict__ Ctx) {
    __shared__ float Qs[64 * 64];
    __shared__ float Kbuf[64 * 64];
    __shared__ float Vs[64 * 64];

    const int q0 = blockIdx.x * 64;
    const int h = blockIdx.y;
    const int b = blockIdx.z;
    const int tid = threadIdx.x;
    const int tx = tid & 15;
    const int ty = tid >> 4;
    const int lrow = tid >> 4;
    const int lcol = (tid & 15) * 4;

    const size_t head_off = ((size_t)b * SS) * DD + (size_t)h * HDIM;
    const float* qbase = Qg + head_off + (size_t)q0 * DD;
    const float* kbase = Kg + head_off;
    const float* vbase = Vg + head_off;

#pragma unroll
    for (int r = 0; r < 64; r += 16) {
        *(float4*)&Qs[(r + lrow) * 64 + lcol] =
            *(const float4*)&qbase[(size_t)(r + lrow) * DD + lcol];
    }

    float o[4][4];
    float m_i[4], l_i[4];
#pragma unroll
    for (int i = 0; i < 4; i++) {
        m_i[i] = -1e30f;
        l_i[i] = 0.f;
#pragma unroll
        for (int j = 0; j < 4; j++) o[i][j] = 0.f;
    }

    const int ktiles = min(q0 / 64 + 2, SS / 64);
    __syncthreads();

    for (int t = 0; t < ktiles; t++) {
        const int k0 = t * 64;
        const float* kb = kbase + (size_t)k0 * DD;
        const float* vb = vbase + (size_t)k0 * DD;

#pragma unroll
        for (int r = 0; r < 64; r += 16) {
            const int krow = r + lrow;
            float4 kv = *(const float4*)&kb[(size_t)krow * DD + lcol];
            Kbuf[krow * 64 + ((lcol + 0 + krow) & 63)] = kv.x;
            Kbuf[krow * 64 + ((lcol + 1 + krow) & 63)] = kv.y;
            Kbuf[krow * 64 + ((lcol + 2 + krow) & 63)] = kv.z;
            Kbuf[krow * 64 + ((lcol + 3 + krow) & 63)] = kv.w;
            *(float4*)&Vs[krow * 64 + lcol] =
                *(const float4*)&vb[(size_t)krow * DD + lcol];
        }
        __syncthreads();

        float s[4][4];
#pragma unroll
        for (int i = 0; i < 4; i++)
#pragma unroll
            for (int j = 0; j < 4; j++) s[i][j] = 0.f;

#pragma unroll 8
        for (int d = 0; d < 64; d++) {
            float ra[4], rb[4];
#pragma unroll
            for (int i = 0; i < 4; i++) ra[i] = Qs[(ty * 4 + i) * 64 + d];
#pragma unroll
            for (int j = 0; j < 4; j++) {
                const int kr = tx * 4 + j;
                rb[j] = Kbuf[kr * 64 + ((d + kr) & 63)];
            }
#pragma unroll
            for (int i = 0; i < 4; i++)
#pragma unroll
                for (int j = 0; j < 4; j++) s[i][j] += ra[i] * rb[j];
        }

        const bool need_mask = (k0 >= q0);
#pragma unroll
        for (int i = 0; i < 4; i++)
#pragma unroll
            for (int j = 0; j < 4; j++) {
                s[i][j] *= 0.125f;
                if (need_mask && (k0 + tx * 4 + j > q0 + ty * 4 + i + 1))
                    s[i][j] = -1e30f;
            }

        float p[4][4];
#pragma unroll
        for (int i = 0; i < 4; i++) {
            float tmax = fmaxf(fmaxf(s[i][0], s[i][1]), fmaxf(s[i][2], s[i][3]));
#pragma unroll
            for (int off = 8; off; off >>= 1)
                tmax = fmaxf(tmax, __shfl_xor_sync(0xffffffffu, tmax, off));
            const float mnew = fmaxf(m_i[i], tmax);
            const float corr = __expf(m_i[i] - mnew);
            float ps = 0.f;
#pragma unroll
            for (int j = 0; j < 4; j++) {
                p[i][j] = __expf(s[i][j] - mnew);
                ps += p[i][j];
            }
#pragma unroll
            for (int off = 8; off; off >>= 1)
                ps += __shfl_xor_sync(0xffffffffu, ps, off);
            l_i[i] = l_i[i] * corr + ps;
            m_i[i] = mnew;
#pragma unroll
            for (int j = 0; j < 4; j++) o[i][j] *= corr;
        }

        __syncthreads();

#pragma unroll
        for (int i = 0; i < 4; i++) {
            float4 pv;
            pv.x = p[i][0]; pv.y = p[i][1]; pv.z = p[i][2]; pv.w = p[i][3];
            *(float4*)&Kbuf[(ty * 4 + i) * 64 + tx * 4] = pv;
        }
        __syncthreads();

#pragma unroll 4
        for (int kk = 0; kk < 64; kk++) {
            float4 v = *(float4*)&Vs[kk * 64 + tx * 4];
#pragma unroll
            for (int i = 0; i < 4; i++) {
                const float pv = Kbuf[(ty * 4 + i) * 64 + kk];
                o[i][0] += pv * v.x;
                o[i][1] += pv * v.y;
                o[i][2] += pv * v.z;
                o[i][3] += pv * v.w;
            }
        }
        __syncthreads();
    }

    float* cbase = Ctx + head_off + (size_t)q0 * DD;
#pragma unroll
    for (int i = 0; i < 4; i++) {
        const float inv_l = 1.0f / l_i[i];
        float4 v;
        v.x = o[i][0] * inv_l;
        v.y = o[i][1] * inv_l;
        v.z = o[i][2] * inv_l;
        v.w = o[i][3] * inv_l;
        *(float4*)&cbase[(size_t)(ty * 4 + i) * DD + tx * 4] = v;
    }
}

// ---------------------------------------------------------------------------
// kernel_launch
// ---------------------------------------------------------------------------
extern "C" void kernel_launch(void* const* d_in, const int* in_sizes, int n_in,
                              void* d_out, int out_size) {
    (void)in_sizes; (void)n_in; (void)out_size;
    const float* x  = (const float*)d_in[0];
    const float* Wq = (const float*)d_in[1];
    const float* Wk = (const float*)d_in[2];
    const float* Wv = (const float*)d_in[3];
    const float* Wo = (const float*)d_in[4];
    const float* bo = (const float*)d_in[5];
    float* out = (float*)d_out;

    float *q, *k, *v, *ctx;
    __nv_bfloat16 *xh, *xl, *ch, *cl, *wh, *wl;
    cudaGetSymbolAddress((void**)&q, g_q);
    cudaGetSymbolAddress((void**)&k, g_k);
    cudaGetSymbolAddress((void**)&v, g_v);
    cudaGetSymbolAddress((void**)&ctx, g_ctx);
    cudaGetSymbolAddress((void**)&xh, g_xh);
    cudaGetSymbolAddress((void**)&xl, g_xl);
    cudaGetSymbolAddress((void**)&ch, g_ch);
    cudaGetSymbolAddress((void**)&cl, g_cl);
    cudaGetSymbolAddress((void**)&wh, g_wh);
    cudaGetSymbolAddress((void**)&wl, g_wl);

    // Prep: split x, transpose+split all 4 weight matrices
    const int n4 = MM * DD / 4;
    cvt_split_kernel<<<(n4 + 255) / 256, 256>>>(x, xh, xl, n4);
    dim3 tgrid(DD / 32, DD / 32), tblk(32, 8);
    wsplit_t_kernel<<<tgrid, tblk>>>(Wq, wh + 0 * DD * DD, wl + 0 * DD * DD);
    wsplit_t_kernel<<<tgrid, tblk>>>(Wk, wh + 1 * DD * DD, wl + 1 * DD * DD);
    wsplit_t_kernel<<<tgrid, tblk>>>(Wv, wh + 2 * DD * DD, wl + 2 * DD * DD);
    wsplit_t_kernel<<<tgrid, tblk>>>(Wo, wh + 3 * DD * DD, wl + 3 * DD * DD);

    // Projections on HMMA (mma.sync bf16 split)
    dim3 ggrid(DD / 128, MM / 128);  // (8, 64)
    gemm_mma<false><<<ggrid, 256, GEMM_SMEM>>>(xh, xl, wh + 0 * DD * DD, wl + 0 * DD * DD, nullptr, q);
    gemm_mma<false><<<ggrid, 256, GEMM_SMEM>>>(xh, xl, wh + 1 * DD * DD, wl + 1 * DD * DD, nullptr, k);
    gemm_mma<false><<<ggrid, 256, GEMM_SMEM>>>(xh, xl, wh + 2 * DD * DD, wl + 2 * DD * DD, nullptr, v);

    // Attention (fp32 FFMA, unchanged)
    dim3 attn_grid(SS / 64, HH, BB);
    attn_kernel<<<attn_grid, 256>>>(q, k, v, ctx);

    // Split ctx, output projection with bias
    cvt_split_kernel<<<(n4 + 255) / 256, 256>>>(ctx, ch, cl, n4);
    gemm_mma<true><<<ggrid, 256, GEMM_SMEM>>>(ch, cl, wh + 3 * DD * DD, wl + 3 * DD * DD, bo, out);
}

// round 10
// speedup vs baseline: 1.7618x; 1.7618x over previous
#include <cuda_runtime.h>
#include <cuda_bf16.h>
#include <cstdint>

// Problem constants
#define BB 4
#define SS 2048
#define DD 1024
#define HH 16
#define HDIM 64
#define MM (BB * SS)   // 8192

// ---------------------------------------------------------------------------
// Static device scratch (no runtime allocation allowed)
// ---------------------------------------------------------------------------
__device__ float g_v[MM * DD];                 // fp32 V (pre-transpose)

__device__ __nv_bfloat16 g_xh[MM * DD];
__device__ __nv_bfloat16 g_xl[MM * DD];
__device__ __nv_bfloat16 g_qh[MM * DD];
__device__ __nv_bfloat16 g_ql[MM * DD];
__device__ __nv_bfloat16 g_kh[MM * DD];
__device__ __nv_bfloat16 g_kl[MM * DD];
__device__ __nv_bfloat16 g_vth[DD * MM];       // V^T hi: [DD][MM]
__device__ __nv_bfloat16 g_vtl[DD * MM];       // V^T lo
__device__ __nv_bfloat16 g_ch[MM * DD];
__device__ __nv_bfloat16 g_cl[MM * DD];
__device__ __nv_bfloat16 g_wh[4][DD * DD];     // transposed W hi: [N][K]
__device__ __nv_bfloat16 g_wl[4][DD * DD];     // transposed W lo: [N][K]

// ---------------------------------------------------------------------------
// PTX helpers (arch-agnostic: cp.async + ldmatrix + mma.sync only)
// ---------------------------------------------------------------------------
__device__ __forceinline__ uint32_t smem_u32(const void* p) {
    return (uint32_t)__cvta_generic_to_shared(p);
}

__device__ __forceinline__ void cp16(uint32_t dst, const void* src) {
    asm volatile("cp.async.cg.shared.global [%0], [%1], 16;" :: "r"(dst), "l"(src));
}

__device__ __forceinline__ void ldsm4(uint32_t& r0, uint32_t& r1, uint32_t& r2,
                                      uint32_t& r3, uint32_t addr) {
    asm volatile("ldmatrix.sync.aligned.m8n8.x4.shared.b16 {%0,%1,%2,%3}, [%4];"
                 : "=r"(r0), "=r"(r1), "=r"(r2), "=r"(r3) : "r"(addr));
}

__device__ __forceinline__ void mma_bf16(float c[4], uint32_t a0, uint32_t a1,
                                         uint32_t a2, uint32_t a3,
                                         uint32_t b0, uint32_t b1) {
    asm volatile(
        "mma.sync.aligned.m16n8k16.row.col.f32.bf16.bf16.f32 "
        "{%0,%1,%2,%3}, {%4,%5,%6,%7}, {%8,%9}, {%0,%1,%2,%3};"
        : "+f"(c[0]), "+f"(c[1]), "+f"(c[2]), "+f"(c[3])
        : "r"(a0), "r"(a1), "r"(a2), "r"(a3), "r"(b0), "r"(b1));
}

// pack2(lo, hi): bf16x2 with lo in bits[15:0], hi in bits[31:16] (rn rounding)
__device__ __forceinline__ uint32_t pack2(float lo, float hi) {
    uint32_t r;
    asm("cvt.rn.bf16x2.f32 %0, %1, %2;" : "=r"(r) : "f"(hi), "f"(lo));
    return r;
}

// ---------------------------------------------------------------------------
// bf16-split HMMA GEMM: 128x128 CTA tile, 8 warps, double-buffered cp.async.
// OMODE: 0 = fp32 out, 1 = fp32 + bias, 2 = hi/lo bf16 split out.
// ---------------------------------------------------------------------------
#define KC 32
#define ASTRIDE 40
#define OP_ELEMS (128 * ASTRIDE)
#define NSTG 2
#define NCHUNK 96
#define GEMM_SMEM (NSTG * 2 * OP_ELEMS * 2)

template <int OMODE>
__global__ __launch_bounds__(256, 2)
void gemm_mma(const __nv_bfloat16* __restrict__ Ah, const __nv_bfloat16* __restrict__ Al,
              const __nv_bfloat16* __restrict__ Bh, const __nv_bfloat16* __restrict__ Bl,
              const float* __restrict__ bias, float* __restrict__ C,
              __nv_bfloat16* __restrict__ Ch, __nv_bfloat16* __restrict__ Cl) {
    extern __shared__ __align__(16) char dyn_smem[];
    __nv_bfloat16* sm = (__nv_bfloat16*)dyn_smem;

    const int tid = threadIdx.x;
    const int wid = tid >> 5;
    const int lane = tid & 31;
    const int wm = (wid & 3) * 32;
    const int wn = (wid >> 2) * 64;
    const int m0 = blockIdx.y * 128;
    const int n0 = blockIdx.x * 128;

    float acc[2][8][4];
#pragma unroll
    for (int i = 0; i < 2; i++)
#pragma unroll
        for (int j = 0; j < 8; j++)
#pragma unroll
            for (int t = 0; t < 4; t++) acc[i][j][t] = 0.f;

    const int seg0 = tid, seg1 = tid + 256;
    const int r0 = seg0 >> 2, c0 = (seg0 & 3) * 8;
    const int r1 = seg1 >> 2, c1 = (seg1 & 3) * 8;

    auto load_chunk = [&](int c) {
        const int p = c >> 5;
        const int koff = (c & 31) * KC;
        const __nv_bfloat16* Asrc = (p < 2) ? Ah : Al;
        const __nv_bfloat16* Bsrc = (p == 1) ? Bl : Bh;
        __nv_bfloat16* sa = sm + (c & (NSTG - 1)) * 2 * OP_ELEMS;
        __nv_bfloat16* sb = sa + OP_ELEMS;
        cp16(smem_u32(sa + r0 * ASTRIDE + c0), Asrc + (size_t)(m0 + r0) * DD + koff + c0);
        cp16(smem_u32(sa + r1 * ASTRIDE + c1), Asrc + (size_t)(m0 + r1) * DD + koff + c1);
        cp16(smem_u32(sb + r0 * ASTRIDE + c0), Bsrc + (size_t)(n0 + r0) * DD + koff + c0);
        cp16(smem_u32(sb + r1 * ASTRIDE + c1), Bsrc + (size_t)(n0 + r1) * DD + koff + c1);
        asm volatile("cp.async.commit_group;" ::: "memory");
    };

    const int a_row = lane & 15;
    const int a_col = (lane >> 4) * 8;
    const int b_row = (lane & 7) + ((lane >> 4) << 3);
    const int b_col = ((lane >> 3) & 1) * 8;

    load_chunk(0);

    for (int c = 0; c < NCHUNK; c++) {
        if (c + 1 < NCHUNK) {
            load_chunk(c + 1);
            asm volatile("cp.async.wait_group 1;" ::: "memory");
        } else {
            asm volatile("cp.async.wait_group 0;" ::: "memory");
        }
        __syncthreads();

        const __nv_bfloat16* sa = sm + (c & (NSTG - 1)) * 2 * OP_ELEMS;
        const __nv_bfloat16* sb = sa + OP_ELEMS;

#pragma unroll
        for (int ks = 0; ks < 2; ks++) {
            const int k = ks * 16;
            uint32_t a[2][4];
#pragma unroll
            for (int mt = 0; mt < 2; mt++) {
                uint32_t addr = smem_u32(sa + (wm + mt * 16 + a_row) * ASTRIDE + k + a_col);
                ldsm4(a[mt][0], a[mt][1], a[mt][2], a[mt][3], addr);
            }
            uint32_t b[8][2];
#pragma unroll
            for (int np = 0; np < 4; np++) {
                uint32_t addr = smem_u32(sb + (wn + np * 16 + b_row) * ASTRIDE + k + b_col);
                ldsm4(b[2 * np][0], b[2 * np][1], b[2 * np + 1][0], b[2 * np + 1][1], addr);
            }
#pragma unroll
            for (int mt = 0; mt < 2; mt++)
#pragma unroll
                for (int nt = 0; nt < 8; nt++)
                    mma_bf16(acc[mt][nt], a[mt][0], a[mt][1], a[mt][2], a[mt][3],
                             b[nt][0], b[nt][1]);
        }
        __syncthreads();
    }

    const int erow = lane >> 2;
    const int ecol = (lane & 3) * 2;
#pragma unroll
    for (int mt = 0; mt < 2; mt++) {
        const int row = m0 + wm + mt * 16 + erow;
#pragma unroll
        for (int nt = 0; nt < 8; nt++) {
            const int col = n0 + wn + nt * 8 + ecol;
            float v0 = acc[mt][nt][0], v1 = acc[mt][nt][1];
            float v2 = acc[mt][nt][2], v3 = acc[mt][nt][3];
            if (OMODE == 1) {
                v0 += bias[col]; v1 += bias[col + 1];
                v2 += bias[col]; v3 += bias[col + 1];
            }
            if (OMODE == 2) {
                float h0 = __bfloat162float(__float2bfloat16(v0));
                float h1 = __bfloat162float(__float2bfloat16(v1));
                float h2 = __bfloat162float(__float2bfloat16(v2));
                float h3 = __bfloat162float(__float2bfloat16(v3));
                *(uint32_t*)&Ch[(size_t)row * DD + col] = pack2(v0, v1);
                *(uint32_t*)&Cl[(size_t)row * DD + col] = pack2(v0 - h0, v1 - h1);
                *(uint32_t*)&Ch[(size_t)(row + 8) * DD + col] = pack2(v2, v3);
                *(uint32_t*)&Cl[(size_t)(row + 8) * DD + col] = pack2(v2 - h2, v3 - h3);
            } else {
                float2 p0; p0.x = v0; p0.y = v1;
                float2 p1; p1.x = v2; p1.y = v3;
                *(float2*)&C[(size_t)row * DD + col] = p0;
                *(float2*)&C[(size_t)(row + 8) * DD + col] = p1;
            }
        }
    }
}

// ---------------------------------------------------------------------------
// Prep kernels
// ---------------------------------------------------------------------------
__global__ __launch_bounds__(256)
void cvt_split_kernel(const float* __restrict__ in, __nv_bfloat16* __restrict__ hi,
                      __nv_bfloat16* __restrict__ lo, int n4) {
    int i = blockIdx.x * blockDim.x + threadIdx.x;
    if (i >= n4) return;
    float4 v = ((const float4*)in)[i];
    float h0 = __bfloat162float(__float2bfloat16(v.x));
    float h1 = __bfloat162float(__float2bfloat16(v.y));
    float h2 = __bfloat162float(__float2bfloat16(v.z));
    float h3 = __bfloat162float(__float2bfloat16(v.w));
    ((uint32_t*)hi)[2 * i + 0] = pack2(v.x, v.y);
    ((uint32_t*)hi)[2 * i + 1] = pack2(v.z, v.w);
    ((uint32_t*)lo)[2 * i + 0] = pack2(v.x - h0, v.y - h1);
    ((uint32_t*)lo)[2 * i + 1] = pack2(v.z - h2, v.w - h3);
}

__global__ __launch_bounds__(256)
void wsplit_t_kernel(const float* __restrict__ W, __nv_bfloat16* __restrict__ Th,
                     __nv_bfloat16* __restrict__ Tl) {
    __shared__ float t[32][33];
    const int bx = blockIdx.x * 32;
    const int by = blockIdx.y * 32;
    const int x = bx + threadIdx.x;
#pragma unroll
    for (int j = threadIdx.y; j < 32; j += 8)
        t[j][threadIdx.x] = W[(size_t)(by + j) * DD + x];
    __syncthreads();
    const int xo = by + threadIdx.x;
#pragma unroll
    for (int j = threadIdx.y; j < 32; j += 8) {
        float v = t[threadIdx.x][j];
        __nv_bfloat16 h = __float2bfloat16(v);
        Th[(size_t)(bx + j) * DD + xo] = h;
        Tl[(size_t)(bx + j) * DD + xo] = __float2bfloat16(v - __bfloat162float(h));
    }
}

// V [M][DD] fp32 -> V^T hi/lo bf16 [DD][MM]
__global__ __launch_bounds__(256)
void vsplit_t_kernel(const float* __restrict__ V, __nv_bfloat16* __restrict__ Th,
                     __nv_bfloat16* __restrict__ Tl) {
    __shared__ float t[32][33];
    const int bx = blockIdx.x * 32;   // d
    const int by = blockIdx.y * 32;   // m
    const int x = bx + threadIdx.x;
#pragma unroll
    for (int j = threadIdx.y; j < 32; j += 8)
        t[j][threadIdx.x] = V[(size_t)(by + j) * DD + x];
    __syncthreads();
    const int xo = by + threadIdx.x;
#pragma unroll
    for (int j = threadIdx.y; j < 32; j += 8) {
        float v = t[threadIdx.x][j];
        __nv_bfloat16 h = __float2bfloat16(v);
        Th[(size_t)(bx + j) * MM + xo] = h;
        Tl[(size_t)(bx + j) * MM + xo] = __float2bfloat16(v - __bfloat162float(h));
    }
}

// ---------------------------------------------------------------------------
// HMMA flash-attention, bf16 split precision.
//   Q tile 128 (8 warps x m16), K/V tiles 64, double-buffered cp.async.
//   QK^T: QhKh + QhKl + QlKh.  PV: PhVh + PhVl + PlVh (P split in registers).
//   Causal mask with +1 lookahead (k <= q+1). Output: ctx hi/lo bf16.
// ---------------------------------------------------------------------------
#define AST 72                         // bf16 elems per smem row (144B)
#define QTILE_E (128 * AST)            // 9216 elems
#define KVTILE_E (64 * AST)            // 4608 elems
#define ATTN_SMEM_B ((2 * QTILE_E + 8 * KVTILE_E) * 2)  // 110592 B

__global__ __launch_bounds__(256)
void attn_mma(const __nv_bfloat16* __restrict__ qh, const __nv_bfloat16* __restrict__ ql,
              const __nv_bfloat16* __restrict__ kh, const __nv_bfloat16* __restrict__ kl,
              const __nv_bfloat16* __restrict__ vth, const __nv_bfloat16* __restrict__ vtl,
              __nv_bfloat16* __restrict__ ch, __nv_bfloat16* __restrict__ cl) {
    extern __shared__ __align__(16) __nv_bfloat16 asm_[];

    const int tid = threadIdx.x;
    const int wid = tid >> 5;
    const int lane = tid & 31;
    const int qt = blockIdx.x;
    const int h = blockIdx.y;
    const int b = blockIdx.z;
    const int q0 = qt * 128;
    const int wm = wid * 16;
    const int g = lane >> 2;          // fragment row (0..7)
    const int t_ = lane & 3;          // fragment col pair

    const size_t rowQ = (size_t)b * SS + q0;
    const uint32_t smb = smem_u32(asm_);

    // ldmatrix lane addressing (verified pattern from GEMM)
    const int a_row = lane & 15;
    const int a_col = (lane >> 4) * 8;
    const int b_row = (lane & 7) + ((lane >> 4) << 3);
    const int b_col = ((lane >> 3) & 1) * 8;

    // ---- load Q (hi+lo) : 2048 segments of 16B, 8 per thread ----
#pragma unroll
    for (int i = 0; i < 8; i++) {
        int gi = tid + 256 * i;
        int tile = gi >> 10;            // 0=Qh, 1=Ql
        int gg = gi & 1023;
        int row = gg >> 3, sg = gg & 7;
        const __nv_bfloat16* src = (tile ? ql : qh) + (rowQ + row) * DD + h * HDIM + sg * 8;
        cp16(smb + (tile * QTILE_E + row * AST) * 2 + sg * 16, src);
    }

    auto load_kv = [&](int t, int s) {
        const size_t rowK = (size_t)b * SS + t * 64;
        const uint32_t base = smb + (2 * QTILE_E + s * 4 * KVTILE_E) * 2;
#pragma unroll
        for (int i = 0; i < 8; i++) {
            int gi = tid + 256 * i;
            int tile = gi >> 9;         // 0=Kh 1=Kl 2=Vth 3=Vtl
            int gg = gi & 511;
            int row = gg >> 3, sg = gg & 7;
            const __nv_bfloat16* src;
            if (tile == 0)      src = kh + (rowK + row) * DD + h * HDIM + sg * 8;
            else if (tile == 1) src = kl + (rowK + row) * DD + h * HDIM + sg * 8;
            else if (tile == 2) src = vth + (size_t)(h * HDIM + row) * MM + rowK + sg * 8;
            else                src = vtl + (size_t)(h * HDIM + row) * MM + rowK + sg * 8;
            cp16(base + (tile * KVTILE_E + row * AST) * 2 + sg * 16, src);
        }
        asm volatile("cp.async.commit_group;" ::: "memory");
    };

    // Tiles needed: keys up to q0+127+1 = q0+128, i.e. tile (q0+128)/64 = 2qt+2
    // inclusive -> 2qt+3 tiles (capped at SS/64). [Round-9 bug: was 2qt+2.]
    const int ktiles = min(2 * qt + 3, SS / 64);

    load_kv(0, 0);   // Q rides in group 0

    float oacc[8][4];
    float m0 = -1e30f, m1 = -1e30f, l0 = 0.f, l1 = 0.f;
#pragma unroll
    for (int nt = 0; nt < 8; nt++)
#pragma unroll
        for (int e = 0; e < 4; e++) oacc[nt][e] = 0.f;

    for (int t = 0; t < ktiles; t++) {
        if (t + 1 < ktiles) {
            load_kv(t + 1, (t + 1) & 1);
            asm volatile("cp.async.wait_group 1;" ::: "memory");
        } else {
            asm volatile("cp.async.wait_group 0;" ::: "memory");
        }
        __syncthreads();

        const int s = t & 1;
        const int k0 = t * 64;
        const __nv_bfloat16* sQh = asm_;
        const __nv_bfloat16* sQl = asm_ + QTILE_E;
        const __nv_bfloat16* sKh = asm_ + 2 * QTILE_E + s * 4 * KVTILE_E;
        const __nv_bfloat16* sKl = sKh + KVTILE_E;
        const __nv_bfloat16* sVh = sKh + 2 * KVTILE_E;
        const __nv_bfloat16* sVl = sKh + 3 * KVTILE_E;

        // ---- S = Q K^T, 3 split passes ----
        float sacc[8][4];
#pragma unroll
        for (int nt = 0; nt < 8; nt++)
#pragma unroll
            for (int e = 0; e < 4; e++) sacc[nt][e] = 0.f;

#pragma unroll
        for (int pass = 0; pass < 3; pass++) {
            const __nv_bfloat16* A = (pass < 2) ? sQh : sQl;
            const __nv_bfloat16* Bk = (pass == 1) ? sKl : sKh;
#pragma unroll
            for (int ks = 0; ks < 4; ks++) {
                const int k = ks * 16;
                uint32_t a0, a1, a2, a3;
                ldsm4(a0, a1, a2, a3, smem_u32(A + (wm + a_row) * AST + k + a_col));
#pragma unroll
                for (int np = 0; np < 4; np++) {
                    uint32_t b0, b1, b2, b3;
                    ldsm4(b0, b1, b2, b3, smem_u32(Bk + (np * 16 + b_row) * AST + k + b_col));
                    mma_bf16(sacc[2 * np], a0, a1, a2, a3, b0, b1);
                    mma_bf16(sacc[2 * np + 1], a0, a1, a2, a3, b2, b3);
                }
            }
        }

        // ---- scale + mask ----
#pragma unroll
        for (int nt = 0; nt < 8; nt++)
#pragma unroll
            for (int e = 0; e < 4; e++) sacc[nt][e] *= 0.125f;

        const int qr0 = q0 + wm + g;
        if (k0 >= q0) {
#pragma unroll
            for (int nt = 0; nt < 8; nt++) {
                const int c = k0 + nt * 8 + 2 * t_;
                if (c     > qr0 + 1) sacc[nt][0] = -1e30f;
                if (c + 1 > qr0 + 1) sacc[nt][1] = -1e30f;
                if (c     > qr0 + 9) sacc[nt][2] = -1e30f;
                if (c + 1 > qr0 + 9) sacc[nt][3] = -1e30f;
            }
        }

        // ---- online softmax (rows g and g+8) ----
        float mx0 = -1e30f, mx1 = -1e30f;
#pragma unroll
        for (int nt = 0; nt < 8; nt++) {
            mx0 = fmaxf(mx0, fmaxf(sacc[nt][0], sacc[nt][1]));
            mx1 = fmaxf(mx1, fmaxf(sacc[nt][2], sacc[nt][3]));
        }
        mx0 = fmaxf(mx0, __shfl_xor_sync(0xffffffffu, mx0, 1));
        mx0 = fmaxf(mx0, __shfl_xor_sync(0xffffffffu, mx0, 2));
        mx1 = fmaxf(mx1, __shfl_xor_sync(0xffffffffu, mx1, 1));
        mx1 = fmaxf(mx1, __shfl_xor_sync(0xffffffffu, mx1, 2));

        const float mn0 = fmaxf(m0, mx0), mn1 = fmaxf(m1, mx1);
        const float cor0 = __expf(m0 - mn0), cor1 = __expf(m1 - mn1);
        m0 = mn0; m1 = mn1;

        float rs0 = 0.f, rs1 = 0.f;
#pragma unroll
        for (int nt = 0; nt < 8; nt++) {
            sacc[nt][0] = __expf(sacc[nt][0] - mn0); rs0 += sacc[nt][0];
            sacc[nt][1] = __expf(sacc[nt][1] - mn0); rs0 += sacc[nt][1];
            sacc[nt][2] = __expf(sacc[nt][2] - mn1); rs1 += sacc[nt][2];
            sacc[nt][3] = __expf(sacc[nt][3] - mn1); rs1 += sacc[nt][3];
        }
        rs0 += __shfl_xor_sync(0xffffffffu, rs0, 1);
        rs0 += __shfl_xor_sync(0xffffffffu, rs0, 2);
        rs1 += __shfl_xor_sync(0xffffffffu, rs1, 1);
        rs1 += __shfl_xor_sync(0xffffffffu, rs1, 2);
        l0 = l0 * cor0 + rs0;
        l1 = l1 * cor1 + rs1;

#pragma unroll
        for (int nt = 0; nt < 8; nt++) {
            oacc[nt][0] *= cor0; oacc[nt][1] *= cor0;
            oacc[nt][2] *= cor1; oacc[nt][3] *= cor1;
        }

        // ---- O += P V, 3 split passes (P split in registers) ----
#pragma unroll
        for (int ks = 0; ks < 4; ks++) {
            const float* P0 = sacc[2 * ks];
            const float* P1 = sacc[2 * ks + 1];
            float h00 = __bfloat162float(__float2bfloat16(P0[0]));
            float h01 = __bfloat162float(__float2bfloat16(P0[1]));
            float h02 = __bfloat162float(__float2bfloat16(P0[2]));
            float h03 = __bfloat162float(__float2bfloat16(P0[3]));
            float h10 = __bfloat162float(__float2bfloat16(P1[0]));
            float h11 = __bfloat162float(__float2bfloat16(P1[1]));
            float h12 = __bfloat162float(__float2bfloat16(P1[2]));
            float h13 = __bfloat162float(__float2bfloat16(P1[3]));
            uint32_t ah0 = pack2(P0[0], P0[1]);
            uint32_t ah1 = pack2(P0[2], P0[3]);
            uint32_t ah2 = pack2(P1[0], P1[1]);
            uint32_t ah3 = pack2(P1[2], P1[3]);
            uint32_t al0 = pack2(P0[0] - h00, P0[1] - h01);
            uint32_t al1 = pack2(P0[2] - h02, P0[3] - h03);
            uint32_t al2 = pack2(P1[0] - h10, P1[1] - h11);
            uint32_t al3 = pack2(P1[2] - h12, P1[3] - h13);

            const int k = ks * 16;
#pragma unroll
            for (int np = 0; np < 4; np++) {
                uint32_t bh0, bh1, bh2, bh3, bl0, bl1, bl2, bl3;
                ldsm4(bh0, bh1, bh2, bh3, smem_u32(sVh + (np * 16 + b_row) * AST + k + b_col));
                ldsm4(bl0, bl1, bl2, bl3, smem_u32(sVl + (np * 16 + b_row) * AST + k + b_col));
                mma_bf16(oacc[2 * np],     ah0, ah1, ah2, ah3, bh0, bh1);
                mma_bf16(oacc[2 * np + 1], ah0, ah1, ah2, ah3, bh2, bh3);
                mma_bf16(oacc[2 * np],     ah0, ah1, ah2, ah3, bl0, bl1);
                mma_bf16(oacc[2 * np + 1], ah0, ah1, ah2, ah3, bl2, bl3);
                mma_bf16(oacc[2 * np],     al0, al1, al2, al3, bh0, bh1);
                mma_bf16(oacc[2 * np + 1], al0, al1, al2, al3, bh2, bh3);
            }
        }
        __syncthreads();
    }

    // ---- epilogue: normalize, split to hi/lo bf16 ctx ----
    const float il0 = 1.0f / l0, il1 = 1.0f / l1;
    const size_t r0g = (size_t)b * SS + q0 + wm + g;
    const size_t r1g = r0g + 8;
#pragma unroll
    for (int nt = 0; nt < 8; nt++) {
        const int col = h * HDIM + nt * 8 + 2 * t_;
        float f0 = oacc[nt][0] * il0, f1 = oacc[nt][1] * il0;
        float f2 = oacc[nt][2] * il1, f3 = oacc[nt][3] * il1;
        float e0 = __bfloat162float(__float2bfloat16(f0));
        float e1 = __bfloat162float(__float2bfloat16(f1));
        float e2 = __bfloat162float(__float2bfloat16(f2));
        float e3 = __bfloat162float(__float2bfloat16(f3));
        *(uint32_t*)&ch[r0g * DD + col] = pack2(f0, f1);
        *(uint32_t*)&cl[r0g * DD + col] = pack2(f0 - e0, f1 - e1);
        *(uint32_t*)&ch[r1g * DD + col] = pack2(f2, f3);
        *(uint32_t*)&cl[r1g * DD + col] = pack2(f2 - e2, f3 - e3);
    }
}

// ---------------------------------------------------------------------------
// kernel_launch
// ---------------------------------------------------------------------------
extern "C" void kernel_launch(void* const* d_in, const int* in_sizes, int n_in,
                              void* d_out, int out_size) {
    (void)in_sizes; (void)n_in; (void)out_size;
    const float* x  = (const float*)d_in[0];
    const float* Wq = (const float*)d_in[1];
    const float* Wk = (const float*)d_in[2];
    const float* Wv = (const float*)d_in[3];
    const float* Wo = (const float*)d_in[4];
    const float* bo = (const float*)d_in[5];
    float* out = (float*)d_out;

    float* v;
    __nv_bfloat16 *xh, *xl, *qh, *ql, *kh, *kl, *vth, *vtl, *ch, *cl, *wh, *wl;
    cudaGetSymbolAddress((void**)&v, g_v);
    cudaGetSymbolAddress((void**)&xh, g_xh);
    cudaGetSymbolAddress((void**)&xl, g_xl);
    cudaGetSymbolAddress((void**)&qh, g_qh);
    cudaGetSymbolAddress((void**)&ql, g_ql);
    cudaGetSymbolAddress((void**)&kh, g_kh);
    cudaGetSymbolAddress((void**)&kl, g_kl);
    cudaGetSymbolAddress((void**)&vth, g_vth);
    cudaGetSymbolAddress((void**)&vtl, g_vtl);
    cudaGetSymbolAddress((void**)&ch, g_ch);
    cudaGetSymbolAddress((void**)&cl, g_cl);
    cudaGetSymbolAddress((void**)&wh, g_wh);
    cudaGetSymbolAddress((void**)&wl, g_wl);

    cudaFuncSetAttribute(attn_mma, cudaFuncAttributeMaxDynamicSharedMemorySize, ATTN_SMEM_B);

    // Prep
    const int n4 = MM * DD / 4;
    cvt_split_kernel<<<(n4 + 255) / 256, 256>>>(x, xh, xl, n4);
    dim3 tgrid(DD / 32, DD / 32), tblk(32, 8);
    wsplit_t_kernel<<<tgrid, tblk>>>(Wq, wh + 0 * DD * DD, wl + 0 * DD * DD);
    wsplit_t_kernel<<<tgrid, tblk>>>(Wk, wh + 1 * DD * DD, wl + 1 * DD * DD);
    wsplit_t_kernel<<<tgrid, tblk>>>(Wv, wh + 2 * DD * DD, wl + 2 * DD * DD);
    wsplit_t_kernel<<<tgrid, tblk>>>(Wo, wh + 3 * DD * DD, wl + 3 * DD * DD);

    // Projections (Q,K -> split bf16 directly; V -> fp32 then transpose-split)
    dim3 ggrid(DD / 128, MM / 128);
    gemm_mma<2><<<ggrid, 256, GEMM_SMEM>>>(xh, xl, wh + 0 * DD * DD, wl + 0 * DD * DD,
                                           nullptr, nullptr, qh, ql);
    gemm_mma<2><<<ggrid, 256, GEMM_SMEM>>>(xh, xl, wh + 1 * DD * DD, wl + 1 * DD * DD,
                                           nullptr, nullptr, kh, kl);
    gemm_mma<0><<<ggrid, 256, GEMM_SMEM>>>(xh, xl, wh + 2 * DD * DD, wl + 2 * DD * DD,
                                           nullptr, v, nullptr, nullptr);
    dim3 vgrid(DD / 32, MM / 32);
    vsplit_t_kernel<<<vgrid, tblk>>>(v, vth, vtl);

    // Attention (HMMA split)
    dim3 agrid(SS / 128, HH, BB);
    attn_mma<<<agrid, 256, ATTN_SMEM_B>>>(qh, ql, kh, kl, vth, vtl, ch, cl);

    // Output projection (+bias)
    gemm_mma<1><<<ggrid, 256, GEMM_SMEM>>>(ch, cl, wh + 3 * DD * DD, wl + 3 * DD * DD,
                                           bo, out, nullptr, nullptr);
}

// round 11
// speedup vs baseline: 1.8806x; 1.0674x over previous
#include <cuda_runtime.h>
#include <cuda_bf16.h>
#include <cstdint>

// Problem constants
#define BB 4
#define SS 2048
#define DD 1024
#define HH 16
#define HDIM 64
#define MM (BB * SS)   // 8192

// ---------------------------------------------------------------------------
// Static device scratch (no runtime allocation allowed)
// ---------------------------------------------------------------------------
__device__ __nv_bfloat16 g_xh[MM * DD];
__device__ __nv_bfloat16 g_xl[MM * DD];
__device__ __nv_bfloat16 g_qh[MM * DD];
__device__ __nv_bfloat16 g_ql[MM * DD];
__device__ __nv_bfloat16 g_kh[MM * DD];
__device__ __nv_bfloat16 g_kl[MM * DD];
__device__ __nv_bfloat16 g_vth[DD * MM];       // V^T hi: [DD][MM]
__device__ __nv_bfloat16 g_vtl[DD * MM];       // V^T lo
__device__ __nv_bfloat16 g_ch[MM * DD];
__device__ __nv_bfloat16 g_cl[MM * DD];
__device__ __nv_bfloat16 g_wh[4][DD * DD];     // transposed W hi: [N][K]
__device__ __nv_bfloat16 g_wl[4][DD * DD];     // transposed W lo: [N][K]

// ---------------------------------------------------------------------------
// PTX helpers (arch-agnostic: cp.async + ldmatrix + mma.sync only)
// ---------------------------------------------------------------------------
__device__ __forceinline__ uint32_t smem_u32(const void* p) {
    return (uint32_t)__cvta_generic_to_shared(p);
}

__device__ __forceinline__ void cp16(uint32_t dst, const void* src) {
    asm volatile("cp.async.cg.shared.global [%0], [%1], 16;" :: "r"(dst), "l"(src));
}

__device__ __forceinline__ void ldsm4(uint32_t& r0, uint32_t& r1, uint32_t& r2,
                                      uint32_t& r3, uint32_t addr) {
    asm volatile("ldmatrix.sync.aligned.m8n8.x4.shared.b16 {%0,%1,%2,%3}, [%4];"
                 : "=r"(r0), "=r"(r1), "=r"(r2), "=r"(r3) : "r"(addr));
}

__device__ __forceinline__ void mma_bf16(float c[4], uint32_t a0, uint32_t a1,
                                         uint32_t a2, uint32_t a3,
                                         uint32_t b0, uint32_t b1) {
    asm volatile(
        "mma.sync.aligned.m16n8k16.row.col.f32.bf16.bf16.f32 "
        "{%0,%1,%2,%3}, {%4,%5,%6,%7}, {%8,%9}, {%0,%1,%2,%3};"
        : "+f"(c[0]), "+f"(c[1]), "+f"(c[2]), "+f"(c[3])
        : "r"(a0), "r"(a1), "r"(a2), "r"(a3), "r"(b0), "r"(b1));
}

// pack2(lo, hi): bf16x2 with lo in bits[15:0], hi in bits[31:16] (rn rounding)
__device__ __forceinline__ uint32_t pack2(float lo, float hi) {
    uint32_t r;
    asm("cvt.rn.bf16x2.f32 %0, %1, %2;" : "=r"(r) : "f"(hi), "f"(lo));
    return r;
}

// ---------------------------------------------------------------------------
// bf16-split HMMA GEMM: 128x128 CTA tile, 8 warps, 3-stage cp.async pipeline,
// K-chunks of 64 (48 chunks total for 3 split passes).
// OMODE: 0 = fp32 out, 1 = fp32 + bias, 2 = hi/lo bf16 split out,
//        3 = TRANSPOSED hi/lo bf16 split out (V^T [DD][MM]).
// ---------------------------------------------------------------------------
#define KC 64
#define GST 72                         // bf16 elems per smem row (144B)
#define OP_ELEMS (128 * GST)           // per operand per stage (9216 elems)
#define NSTG 3
#define NCHUNK 48                      // 3 passes * (1024/64)
#define GEMM_SMEM (NSTG * 2 * OP_ELEMS * 2)   // 110592 bytes

template <int OMODE>
__global__ __launch_bounds__(256, 2)
void gemm_mma(const __nv_bfloat16* __restrict__ Ah, const __nv_bfloat16* __restrict__ Al,
              const __nv_bfloat16* __restrict__ Bh, const __nv_bfloat16* __restrict__ Bl,
              const float* __restrict__ bias, float* __restrict__ C,
              __nv_bfloat16* __restrict__ Ch, __nv_bfloat16* __restrict__ Cl) {
    extern __shared__ __align__(16) char dyn_smem[];
    __nv_bfloat16* sm = (__nv_bfloat16*)dyn_smem;

    const int tid = threadIdx.x;
    const int wid = tid >> 5;
    const int lane = tid & 31;
    const int wm = (wid & 3) * 32;
    const int wn = (wid >> 2) * 64;
    const int m0 = blockIdx.y * 128;
    const int n0 = blockIdx.x * 128;

    float acc[2][8][4];
#pragma unroll
    for (int i = 0; i < 2; i++)
#pragma unroll
        for (int j = 0; j < 8; j++)
#pragma unroll
            for (int t = 0; t < 4; t++) acc[i][j][t] = 0.f;

    // Per-chunk load geometry: per operand 128 rows x 8 segs of 16B = 1024 segs;
    // thread handles segs tid, tid+256, tid+512, tid+768.
    int rowS[4], sgS[4];
#pragma unroll
    for (int i = 0; i < 4; i++) {
        int seg = tid + 256 * i;
        rowS[i] = seg >> 3;
        sgS[i] = (seg & 7) * 8;
    }

    auto load_chunk = [&](int c) {
        const int p = c >> 4;              // 0: Ah*Bh, 1: Ah*Bl, 2: Al*Bh
        const int koff = (c & 15) * KC;
        const __nv_bfloat16* Asrc = (p < 2) ? Ah : Al;
        const __nv_bfloat16* Bsrc = (p == 1) ? Bl : Bh;
        __nv_bfloat16* sa = sm + (c % NSTG) * 2 * OP_ELEMS;
        __nv_bfloat16* sb = sa + OP_ELEMS;
#pragma unroll
        for (int i = 0; i < 4; i++) {
            cp16(smem_u32(sa + rowS[i] * GST + sgS[i]),
                 Asrc + (size_t)(m0 + rowS[i]) * DD + koff + sgS[i]);
            cp16(smem_u32(sb + rowS[i] * GST + sgS[i]),
                 Bsrc + (size_t)(n0 + rowS[i]) * DD + koff + sgS[i]);
        }
        asm volatile("cp.async.commit_group;" ::: "memory");
    };

    const int a_row = lane & 15;
    const int a_col = (lane >> 4) * 8;
    const int b_row = (lane & 7) + ((lane >> 4) << 3);
    const int b_col = ((lane >> 3) & 1) * 8;

    load_chunk(0);
    load_chunk(1);

    for (int c = 0; c < NCHUNK; c++) {
        if (c + 2 < NCHUNK) {
            load_chunk(c + 2);
            asm volatile("cp.async.wait_group 2;" ::: "memory");
        } else if (c + 1 < NCHUNK) {
            asm volatile("cp.async.wait_group 1;" ::: "memory");
        } else {
            asm volatile("cp.async.wait_group 0;" ::: "memory");
        }
        __syncthreads();

        const __nv_bfloat16* sa = sm + (c % NSTG) * 2 * OP_ELEMS;
        const __nv_bfloat16* sb = sa + OP_ELEMS;

#pragma unroll
        for (int ks = 0; ks < 4; ks++) {
            const int k = ks * 16;
            uint32_t a[2][4];
#pragma unroll
            for (int mt = 0; mt < 2; mt++) {
                uint32_t addr = smem_u32(sa + (wm + mt * 16 + a_row) * GST + k + a_col);
                ldsm4(a[mt][0], a[mt][1], a[mt][2], a[mt][3], addr);
            }
            uint32_t b[8][2];
#pragma unroll
            for (int np = 0; np < 4; np++) {
                uint32_t addr = smem_u32(sb + (wn + np * 16 + b_row) * GST + k + b_col);
                ldsm4(b[2 * np][0], b[2 * np][1], b[2 * np + 1][0], b[2 * np + 1][1], addr);
            }
#pragma unroll
            for (int mt = 0; mt < 2; mt++)
#pragma unroll
                for (int nt = 0; nt < 8; nt++)
                    mma_bf16(acc[mt][nt], a[mt][0], a[mt][1], a[mt][2], a[mt][3],
                             b[nt][0], b[nt][1]);
        }
        __syncthreads();
    }

    const int erow = lane >> 2;
    const int ecol = (lane & 3) * 2;

    if (OMODE == 3) {
        // Transposed split epilogue: stage through smem (64 n-rows x 128 m, pad 132),
        // write V^T[n][m] hi/lo coalesced. Two halves: warps 0-3 own n 0..63,
        // warps 4-7 own n 64..127.
        float* sT = (float*)dyn_smem;
        const int srow = tid >> 2;          // 0..63
        const int scol = (tid & 3) * 32;    // 0,32,64,96
#pragma unroll
        for (int hf = 0; hf < 2; hf++) {
            __syncthreads();
            if ((wid >> 2) == hf) {
#pragma unroll
                for (int mt = 0; mt < 2; mt++) {
                    const int m = wm + mt * 16 + erow;
#pragma unroll
                    for (int nt = 0; nt < 8; nt++) {
                        const int nl = nt * 8 + ecol;   // local n within half
                        sT[(nl + 0) * 132 + m] = acc[mt][nt][0];
                        sT[(nl + 1) * 132 + m] = acc[mt][nt][1];
                        sT[(nl + 0) * 132 + m + 8] = acc[mt][nt][2];
                        sT[(nl + 1) * 132 + m + 8] = acc[mt][nt][3];
                    }
                }
            }
            __syncthreads();
            const size_t n_glob = n0 + hf * 64 + srow;
            const float* sp = sT + srow * 132 + scol;
            __nv_bfloat16* dh = Ch + n_glob * MM + m0 + scol;
            __nv_bfloat16* dl = Cl + n_glob * MM + m0 + scol;
#pragma unroll
            for (int j = 0; j < 32; j += 2) {
                float f0 = sp[j], f1 = sp[j + 1];
                float h0 = __bfloat162float(__float2bfloat16(f0));
                float h1 = __bfloat162float(__float2bfloat16(f1));
                *(uint32_t*)(dh + j) = pack2(f0, f1);
                *(uint32_t*)(dl + j) = pack2(f0 - h0, f1 - h1);
            }
        }
        return;
    }

#pragma unroll
    for (int mt = 0; mt < 2; mt++) {
        const int row = m0 + wm + mt * 16 + erow;
#pragma unroll
        for (int nt = 0; nt < 8; nt++) {
            const int col = n0 + wn + nt * 8 + ecol;
            float v0 = acc[mt][nt][0], v1 = acc[mt][nt][1];
            float v2 = acc[mt][nt][2], v3 = acc[mt][nt][3];
            if (OMODE == 1) {
                v0 += bias[col]; v1 += bias[col + 1];
                v2 += bias[col]; v3 += bias[col + 1];
            }
            if (OMODE == 2) {
                float h0 = __bfloat162float(__float2bfloat16(v0));
                float h1 = __bfloat162float(__float2bfloat16(v1));
                float h2 = __bfloat162float(__float2bfloat16(v2));
                float h3 = __bfloat162float(__float2bfloat16(v3));
                *(uint32_t*)&Ch[(size_t)row * DD + col] = pack2(v0, v1);
                *(uint32_t*)&Cl[(size_t)row * DD + col] = pack2(v0 - h0, v1 - h1);
                *(uint32_t*)&Ch[(size_t)(row + 8) * DD + col] = pack2(v2, v3);
                *(uint32_t*)&Cl[(size_t)(row + 8) * DD + col] = pack2(v2 - h2, v3 - h3);
            } else {
                float2 p0; p0.x = v0; p0.y = v1;
                float2 p1; p1.x = v2; p1.y = v3;
                *(float2*)&C[(size_t)row * DD + col] = p0;
                *(float2*)&C[(size_t)(row + 8) * DD + col] = p1;
            }
        }
    }
}

// ---------------------------------------------------------------------------
// Prep kernels
// ---------------------------------------------------------------------------
__global__ __launch_bounds__(256)
void cvt_split_kernel(const float* __restrict__ in, __nv_bfloat16* __restrict__ hi,
                      __nv_bfloat16* __restrict__ lo, int n4) {
    int i = blockIdx.x * blockDim.x + threadIdx.x;
    if (i >= n4) return;
    float4 v = ((const float4*)in)[i];
    float h0 = __bfloat162float(__float2bfloat16(v.x));
    float h1 = __bfloat162float(__float2bfloat16(v.y));
    float h2 = __bfloat162float(__float2bfloat16(v.z));
    float h3 = __bfloat162float(__float2bfloat16(v.w));
    ((uint32_t*)hi)[2 * i + 0] = pack2(v.x, v.y);
    ((uint32_t*)hi)[2 * i + 1] = pack2(v.z, v.w);
    ((uint32_t*)lo)[2 * i + 0] = pack2(v.x - h0, v.y - h1);
    ((uint32_t*)lo)[2 * i + 1] = pack2(v.z - h2, v.w - h3);
}

__global__ __launch_bounds__(256)
void wsplit_t_kernel(const float* __restrict__ W, __nv_bfloat16* __restrict__ Th,
                     __nv_bfloat16* __restrict__ Tl) {
    __shared__ float t[32][33];
    const int bx = blockIdx.x * 32;
    const int by = blockIdx.y * 32;
    const int x = bx + threadIdx.x;
#pragma unroll
    for (int j = threadIdx.y; j < 32; j += 8)
        t[j][threadIdx.x] = W[(size_t)(by + j) * DD + x];
    __syncthreads();
    const int xo = by + threadIdx.x;
#pragma unroll
    for (int j = threadIdx.y; j < 32; j += 8) {
        float v = t[threadIdx.x][j];
        __nv_bfloat16 h = __float2bfloat16(v);
        Th[(size_t)(bx + j) * DD + xo] = h;
        Tl[(size_t)(bx + j) * DD + xo] = __float2bfloat16(v - __bfloat162float(h));
    }
}

// ---------------------------------------------------------------------------
// HMMA flash-attention, bf16 split precision (as round 10, + lookahead skip).
// ---------------------------------------------------------------------------
#define AST 72
#define QTILE_E (128 * AST)
#define KVTILE_E (64 * AST)
#define ATTN_SMEM_B ((2 * QTILE_E + 8 * KVTILE_E) * 2)  // 110592 B

__global__ __launch_bounds__(256)
void attn_mma(const __nv_bfloat16* __restrict__ qh, const __nv_bfloat16* __restrict__ ql,
              const __nv_bfloat16* __restrict__ kh, const __nv_bfloat16* __restrict__ kl,
              const __nv_bfloat16* __restrict__ vth, const __nv_bfloat16* __restrict__ vtl,
              __nv_bfloat16* __restrict__ ch, __nv_bfloat16* __restrict__ cl) {
    extern __shared__ __align__(16) __nv_bfloat16 asm_[];

    const int tid = threadIdx.x;
    const int wid = tid >> 5;
    const int lane = tid & 31;
    const int qt = blockIdx.x;
    const int h = blockIdx.y;
    const int b = blockIdx.z;
    const int q0 = qt * 128;
    const int wm = wid * 16;
    const int g = lane >> 2;
    const int t_ = lane & 3;

    const size_t rowQ = (size_t)b * SS + q0;
    const uint32_t smb = smem_u32(asm_);

    const int a_row = lane & 15;
    const int a_col = (lane >> 4) * 8;
    const int b_row = (lane & 7) + ((lane >> 4) << 3);
    const int b_col = ((lane >> 3) & 1) * 8;

#pragma unroll
    for (int i = 0; i < 8; i++) {
        int gi = tid + 256 * i;
        int tile = gi >> 10;
        int gg = gi & 1023;
        int row = gg >> 3, sg = gg & 7;
        const __nv_bfloat16* src = (tile ? ql : qh) + (rowQ + row) * DD + h * HDIM + sg * 8;
        cp16(smb + (tile * QTILE_E + row * AST) * 2 + sg * 16, src);
    }

    auto load_kv = [&](int t, int s) {
        const size_t rowK = (size_t)b * SS + t * 64;
        const uint32_t base = smb + (2 * QTILE_E + s * 4 * KVTILE_E) * 2;
#pragma unroll
        for (int i = 0; i < 8; i++) {
            int gi = tid + 256 * i;
            int tile = gi >> 9;
            int gg = gi & 511;
            int row = gg >> 3, sg = gg & 7;
            const __nv_bfloat16* src;
            if (tile == 0)      src = kh + (rowK + row) * DD + h * HDIM + sg * 8;
            else if (tile == 1) src = kl + (rowK + row) * DD + h * HDIM + sg * 8;
            else if (tile == 2) src = vth + (size_t)(h * HDIM + row) * MM + rowK + sg * 8;
            else                src = vtl + (size_t)(h * HDIM + row) * MM + rowK + sg * 8;
            cp16(base + (tile * KVTILE_E + row * AST) * 2 + sg * 16, src);
        }
        asm volatile("cp.async.commit_group;" ::: "memory");
    };

    const int ktiles = min(2 * qt + 3, SS / 64);

    load_kv(0, 0);

    float oacc[8][4];
    float m0 = -1e30f, m1 = -1e30f, l0 = 0.f, l1 = 0.f;
#pragma unroll
    for (int nt = 0; nt < 8; nt++)
#pragma unroll
        for (int e = 0; e < 4; e++) oacc[nt][e] = 0.f;

    for (int t = 0; t < ktiles; t++) {
        if (t + 1 < ktiles) {
            load_kv(t + 1, (t + 1) & 1);
            asm volatile("cp.async.wait_group 1;" ::: "memory");
        } else {
            asm volatile("cp.async.wait_group 0;" ::: "memory");
        }
        __syncthreads();

        const int s = t & 1;
        const int k0 = t * 64;
        // Pure-lookahead tile: only query row q0+127 (warp 7) has unmasked work;
        // for other warps every p underflows to exactly 0, so skipping is exact.
        const bool skip = (k0 > q0 + 127) && (wid != 7);

        if (!skip) {
            const __nv_bfloat16* sQh = asm_;
            const __nv_bfloat16* sQl = asm_ + QTILE_E;
            const __nv_bfloat16* sKh = asm_ + 2 * QTILE_E + s * 4 * KVTILE_E;
            const __nv_bfloat16* sKl = sKh + KVTILE_E;
            const __nv_bfloat16* sVh = sKh + 2 * KVTILE_E;
            const __nv_bfloat16* sVl = sKh + 3 * KVTILE_E;

            float sacc[8][4];
#pragma unroll
            for (int nt = 0; nt < 8; nt++)
#pragma unroll
                for (int e = 0; e < 4; e++) sacc[nt][e] = 0.f;

#pragma unroll
            for (int pass = 0; pass < 3; pass++) {
                const __nv_bfloat16* A = (pass < 2) ? sQh : sQl;
                const __nv_bfloat16* Bk = (pass == 1) ? sKl : sKh;
#pragma unroll
                for (int ks = 0; ks < 4; ks++) {
                    const int k = ks * 16;
                    uint32_t a0, a1, a2, a3;
                    ldsm4(a0, a1, a2, a3, smem_u32(A + (wm + a_row) * AST + k + a_col));
#pragma unroll
                    for (int np = 0; np < 4; np++) {
                        uint32_t b0, b1, b2, b3;
                        ldsm4(b0, b1, b2, b3, smem_u32(Bk + (np * 16 + b_row) * AST + k + b_col));
                        mma_bf16(sacc[2 * np], a0, a1, a2, a3, b0, b1);
                        mma_bf16(sacc[2 * np + 1], a0, a1, a2, a3, b2, b3);
                    }
                }
            }

#pragma unroll
            for (int nt = 0; nt < 8; nt++)
#pragma unroll
                for (int e = 0; e < 4; e++) sacc[nt][e] *= 0.125f;

            const int qr0 = q0 + wm + g;
            if (k0 >= q0) {
#pragma unroll
                for (int nt = 0; nt < 8; nt++) {
                    const int c = k0 + nt * 8 + 2 * t_;
                    if (c     > qr0 + 1) sacc[nt][0] = -1e30f;
                    if (c + 1 > qr0 + 1) sacc[nt][1] = -1e30f;
                    if (c     > qr0 + 9) sacc[nt][2] = -1e30f;
                    if (c + 1 > qr0 + 9) sacc[nt][3] = -1e30f;
                }
            }

            float mx0 = -1e30f, mx1 = -1e30f;
#pragma unroll
            for (int nt = 0; nt < 8; nt++) {
                mx0 = fmaxf(mx0, fmaxf(sacc[nt][0], sacc[nt][1]));
                mx1 = fmaxf(mx1, fmaxf(sacc[nt][2], sacc[nt][3]));
            }
            mx0 = fmaxf(mx0, __shfl_xor_sync(0xffffffffu, mx0, 1));
            mx0 = fmaxf(mx0, __shfl_xor_sync(0xffffffffu, mx0, 2));
            mx1 = fmaxf(mx1, __shfl_xor_sync(0xffffffffu, mx1, 1));
            mx1 = fmaxf(mx1, __shfl_xor_sync(0xffffffffu, mx1, 2));

            const float mn0 = fmaxf(m0, mx0), mn1 = fmaxf(m1, mx1);
            const float cor0 = __expf(m0 - mn0), cor1 = __expf(m1 - mn1);
            m0 = mn0; m1 = mn1;

            float rs0 = 0.f, rs1 = 0.f;
#pragma unroll
            for (int nt = 0; nt < 8; nt++) {
                sacc[nt][0] = __expf(sacc[nt][0] - mn0); rs0 += sacc[nt][0];
                sacc[nt][1] = __expf(sacc[nt][1] - mn0); rs0 += sacc[nt][1];
                sacc[nt][2] = __expf(sacc[nt][2] - mn1); rs1 += sacc[nt][2];
                sacc[nt][3] = __expf(sacc[nt][3] - mn1); rs1 += sacc[nt][3];
            }
            rs0 += __shfl_xor_sync(0xffffffffu, rs0, 1);
            rs0 += __shfl_xor_sync(0xffffffffu, rs0, 2);
            rs1 += __shfl_xor_sync(0xffffffffu, rs1, 1);
            rs1 += __shfl_xor_sync(0xffffffffu, rs1, 2);
            l0 = l0 * cor0 + rs0;
            l1 = l1 * cor1 + rs1;

#pragma unroll
            for (int nt = 0; nt < 8; nt++) {
                oacc[nt][0] *= cor0; oacc[nt][1] *= cor0;
                oacc[nt][2] *= cor1; oacc[nt][3] *= cor1;
            }

#pragma unroll
            for (int ks = 0; ks < 4; ks++) {
                const float* P0 = sacc[2 * ks];
                const float* P1 = sacc[2 * ks + 1];
                float h00 = __bfloat162float(__float2bfloat16(P0[0]));
                float h01 = __bfloat162float(__float2bfloat16(P0[1]));
                float h02 = __bfloat162float(__float2bfloat16(P0[2]));
                float h03 = __bfloat162float(__float2bfloat16(P0[3]));
                float h10 = __bfloat162float(__float2bfloat16(P1[0]));
                float h11 = __bfloat162float(__float2bfloat16(P1[1]));
                float h12 = __bfloat162float(__float2bfloat16(P1[2]));
                float h13 = __bfloat162float(__float2bfloat16(P1[3]));
                uint32_t ah0 = pack2(P0[0], P0[1]);
                uint32_t ah1 = pack2(P0[2], P0[3]);
                uint32_t ah2 = pack2(P1[0], P1[1]);
                uint32_t ah3 = pack2(P1[2], P1[3]);
                uint32_t al0 = pack2(P0[0] - h00, P0[1] - h01);
                uint32_t al1 = pack2(P0[2] - h02, P0[3] - h03);
                uint32_t al2 = pack2(P1[0] - h10, P1[1] - h11);
                uint32_t al3 = pack2(P1[2] - h12, P1[3] - h13);

                const int k = ks * 16;
#pragma unroll
                for (int np = 0; np < 4; np++) {
                    uint32_t bh0, bh1, bh2, bh3, bl0, bl1, bl2, bl3;
                    ldsm4(bh0, bh1, bh2, bh3, smem_u32(sVh + (np * 16 + b_row) * AST + k + b_col));
                    ldsm4(bl0, bl1, bl2, bl3, smem_u32(sVl + (np * 16 + b_row) * AST + k + b_col));
                    mma_bf16(oacc[2 * np],     ah0, ah1, ah2, ah3, bh0, bh1);
                    mma_bf16(oacc[2 * np + 1], ah0, ah1, ah2, ah3, bh2, bh3);
                    mma_bf16(oacc[2 * np],     ah0, ah1, ah2, ah3, bl0, bl1);
                    mma_bf16(oacc[2 * np + 1], ah0, ah1, ah2, ah3, bl2, bl3);
                    mma_bf16(oacc[2 * np],     al0, al1, al2, al3, bh0, bh1);
                    mma_bf16(oacc[2 * np + 1], al0, al1, al2, al3, bh2, bh3);
                }
            }
        }
        __syncthreads();
    }

    const float il0 = 1.0f / l0, il1 = 1.0f / l1;
    const size_t r0g = (size_t)b * SS + q0 + wm + g;
    const size_t r1g = r0g + 8;
#pragma unroll
    for (int nt = 0; nt < 8; nt++) {
        const int col = h * HDIM + nt * 8 + 2 * t_;
        float f0 = oacc[nt][0] * il0, f1 = oacc[nt][1] * il0;
        float f2 = oacc[nt][2] * il1, f3 = oacc[nt][3] * il1;
        float e0 = __bfloat162float(__float2bfloat16(f0));
        float e1 = __bfloat162float(__float2bfloat16(f1));
        float e2 = __bfloat162float(__float2bfloat16(f2));
        float e3 = __bfloat162float(__float2bfloat16(f3));
        *(uint32_t*)&ch[r0g * DD + col] = pack2(f0, f1);
        *(uint32_t*)&cl[r0g * DD + col] = pack2(f0 - e0, f1 - e1);
        *(uint32_t*)&ch[r1g * DD + col] = pack2(f2, f3);
        *(uint32_t*)&cl[r1g * DD + col] = pack2(f2 - e2, f3 - e3);
    }
}

// ---------------------------------------------------------------------------
// kernel_launch
// ---------------------------------------------------------------------------
extern "C" void kernel_launch(void* const* d_in, const int* in_sizes, int n_in,
                              void* d_out, int out_size) {
    (void)in_sizes; (void)n_in; (void)out_size;
    const float* x  = (const float*)d_in[0];
    const float* Wq = (const float*)d_in[1];
    const float* Wk = (const float*)d_in[2];
    const float* Wv = (const float*)d_in[3];
    const float* Wo = (const float*)d_in[4];
    const float* bo = (const float*)d_in[5];
    float* out = (float*)d_out;

    __nv_bfloat16 *xh, *xl, *qh, *ql, *kh, *kl, *vth, *vtl, *ch, *cl, *wh, *wl;
    cudaGetSymbolAddress((void**)&xh, g_xh);
    cudaGetSymbolAddress((void**)&xl, g_xl);
    cudaGetSymbolAddress((void**)&qh, g_qh);
    cudaGetSymbolAddress((void**)&ql, g_ql);
    cudaGetSymbolAddress((void**)&kh, g_kh);
    cudaGetSymbolAddress((void**)&kl, g_kl);
    cudaGetSymbolAddress((void**)&vth, g_vth);
    cudaGetSymbolAddress((void**)&vtl, g_vtl);
    cudaGetSymbolAddress((void**)&ch, g_ch);
    cudaGetSymbolAddress((void**)&cl, g_cl);
    cudaGetSymbolAddress((void**)&wh, g_wh);
    cudaGetSymbolAddress((void**)&wl, g_wl);

    cudaFuncSetAttribute(attn_mma, cudaFuncAttributeMaxDynamicSharedMemorySize, ATTN_SMEM_B);
    cudaFuncSetAttribute(gemm_mma<1>, cudaFuncAttributeMaxDynamicSharedMemorySize, GEMM_SMEM);
    cudaFuncSetAttribute(gemm_mma<2>, cudaFuncAttributeMaxDynamicSharedMemorySize, GEMM_SMEM);
    cudaFuncSetAttribute(gemm_mma<3>, cudaFuncAttributeMaxDynamicSharedMemorySize, GEMM_SMEM);

    // Prep
    const int n4 = MM * DD / 4;
    cvt_split_kernel<<<(n4 + 255) / 256, 256>>>(x, xh, xl, n4);
    dim3 tgrid(DD / 32, DD / 32), tblk(32, 8);
    wsplit_t_kernel<<<tgrid, tblk>>>(Wq, wh + 0 * DD * DD, wl + 0 * DD * DD);
    wsplit_t_kernel<<<tgrid, tblk>>>(Wk, wh + 1 * DD * DD, wl + 1 * DD * DD);
    wsplit_t_kernel<<<tgrid, tblk>>>(Wv, wh + 2 * DD * DD, wl + 2 * DD * DD);
    wsplit_t_kernel<<<tgrid, tblk>>>(Wo, wh + 3 * DD * DD, wl + 3 * DD * DD);

    // Projections (Q,K -> split bf16; V -> transposed split bf16, fused)
    dim3 ggrid(DD / 128, MM / 128);
    gemm_mma<2><<<ggrid, 256, GEMM_SMEM>>>(xh, xl, wh + 0 * DD * DD, wl + 0 * DD * DD,
                                           nullptr, nullptr, qh, ql);
    gemm_mma<2><<<ggrid, 256, GEMM_SMEM>>>(xh, xl, wh + 1 * DD * DD, wl + 1 * DD * DD,
                                           nullptr, nullptr, kh, kl);
    gemm_mma<3><<<ggrid, 256, GEMM_SMEM>>>(xh, xl, wh + 2 * DD * DD, wl + 2 * DD * DD,
                                           nullptr, nullptr, vth, vtl);

    // Attention (HMMA split)
    dim3 agrid(SS / 128, HH, BB);
    attn_mma<<<agrid, 256, ATTN_SMEM_B>>>(qh, ql, kh, kl, vth, vtl, ch, cl);

    // Output projection (+bias)
    gemm_mma<1><<<ggrid, 256, GEMM_SMEM>>>(ch, cl, wh + 3 * DD * DD, wl + 3 * DD * DD,
                                           bo, out, nullptr, nullptr);
}

// round 12
// speedup vs baseline: 2.1199x; 1.1273x over previous
#include <cuda_runtime.h>
#include <cuda_bf16.h>
#include <cstdint>

// Problem constants
#define BB 4
#define SS 2048
#define DD 1024
#define HH 16
#define HDIM 64
#define MM (BB * SS)   // 8192

// ---------------------------------------------------------------------------
// Static device scratch (no runtime allocation allowed)
// ---------------------------------------------------------------------------
__device__ __nv_bfloat16 g_xh[MM * DD];
__device__ __nv_bfloat16 g_xl[MM * DD];
__device__ __nv_bfloat16 g_qh[MM * DD];
__device__ __nv_bfloat16 g_ql[MM * DD];
__device__ __nv_bfloat16 g_kh[MM * DD];
__device__ __nv_bfloat16 g_kl[MM * DD];
__device__ __nv_bfloat16 g_vth[DD * MM];       // V^T hi: [DD][MM]
__device__ __nv_bfloat16 g_vtl[DD * MM];       // V^T lo
__device__ __nv_bfloat16 g_ch[MM * DD];
__device__ __nv_bfloat16 g_cl[MM * DD];
__device__ __nv_bfloat16 g_wh[4][DD * DD];     // transposed W hi: [N][K]
__device__ __nv_bfloat16 g_wl[4][DD * DD];     // transposed W lo: [N][K]

// ---------------------------------------------------------------------------
// PTX helpers
// ---------------------------------------------------------------------------
__device__ __forceinline__ uint32_t smem_u32(const void* p) {
    return (uint32_t)__cvta_generic_to_shared(p);
}

__device__ __forceinline__ void cp16(uint32_t dst, const void* src) {
    asm volatile("cp.async.cg.shared.global [%0], [%1], 16;" :: "r"(dst), "l"(src));
}

__device__ __forceinline__ void ldsm4(uint32_t& r0, uint32_t& r1, uint32_t& r2,
                                      uint32_t& r3, uint32_t addr) {
    asm volatile("ldmatrix.sync.aligned.m8n8.x4.shared.b16 {%0,%1,%2,%3}, [%4];"
                 : "=r"(r0), "=r"(r1), "=r"(r2), "=r"(r3) : "r"(addr));
}

__device__ __forceinline__ void mma_bf16(float c[4], uint32_t a0, uint32_t a1,
                                         uint32_t a2, uint32_t a3,
                                         uint32_t b0, uint32_t b1) {
    asm volatile(
        "mma.sync.aligned.m16n8k16.row.col.f32.bf16.bf16.f32 "
        "{%0,%1,%2,%3}, {%4,%5,%6,%7}, {%8,%9}, {%0,%1,%2,%3};"
        : "+f"(c[0]), "+f"(c[1]), "+f"(c[2]), "+f"(c[3])
        : "r"(a0), "r"(a1), "r"(a2), "r"(a3), "r"(b0), "r"(b1));
}

// pack2(lo, hi): bf16x2, lo in bits[15:0], hi in bits[31:16]
__device__ __forceinline__ uint32_t pack2(float lo, float hi) {
    uint32_t r;
    asm("cvt.rn.bf16x2.f32 %0, %1, %2;" : "=r"(r) : "f"(hi), "f"(lo));
    return r;
}

// SW128 swizzle for 128B rows: row-relative byte offset of 16B segment sg (0..7)
__device__ __forceinline__ uint32_t swz(int row, int sg) {
    return (uint32_t)(row * 128 + (((sg ^ row) & 7) << 4));
}

// ---------------------------------------------------------------------------
// bf16-split HMMA GEMM: 128x128 CTA tile, 8 warps, 3-stage cp.async pipeline,
// K-chunks of 64, SW128-swizzled smem (128B rows, no padding).
// OMODE: 0 = fp32 out, 1 = fp32 + bias, 2 = hi/lo bf16 split out,
//        3 = TRANSPOSED hi/lo bf16 split out (V^T [DD][MM]).
// ---------------------------------------------------------------------------
#define KC 64
#define OPB 16384                    // bytes per operand per stage (128 x 128B)
#define STGB (2 * OPB)               // 32768
#define NSTG 3
#define NCHUNK 48                    // 3 passes * (1024/64)
#define GEMM_SMEM (NSTG * STGB)      // 98304 bytes

template <int OMODE>
__global__ __launch_bounds__(256, 2)
void gemm_mma(const __nv_bfloat16* __restrict__ Ah, const __nv_bfloat16* __restrict__ Al,
              const __nv_bfloat16* __restrict__ Bh, const __nv_bfloat16* __restrict__ Bl,
              const float* __restrict__ bias, float* __restrict__ C,
              __nv_bfloat16* __restrict__ Ch, __nv_bfloat16* __restrict__ Cl) {
    extern __shared__ __align__(16) char dyn_smem[];
    const uint32_t smb = smem_u32(dyn_smem);

    const int tid = threadIdx.x;
    const int wid = tid >> 5;
    const int lane = tid & 31;
    const int wm = (wid & 3) * 32;
    const int wn = (wid >> 2) * 64;
    const int m0 = blockIdx.y * 128;
    const int n0 = blockIdx.x * 128;

    float acc[2][8][4];
#pragma unroll
    for (int i = 0; i < 2; i++)
#pragma unroll
        for (int j = 0; j < 8; j++)
#pragma unroll
            for (int t = 0; t < 4; t++) acc[i][j][t] = 0.f;

    // Load geometry: per operand 128 rows x 8 segs(16B); thread owns 4 segs.
    int rowS[4], sgI[4];
#pragma unroll
    for (int i = 0; i < 4; i++) {
        int seg = tid + 256 * i;
        rowS[i] = seg >> 3;
        sgI[i] = seg & 7;
    }

    auto load_chunk = [&](int c) {
        const int p = c >> 4;              // 0: Ah*Bh, 1: Ah*Bl, 2: Al*Bh
        const int koff = (c & 15) * KC;
        const __nv_bfloat16* Asrc = (p < 2) ? Ah : Al;
        const __nv_bfloat16* Bsrc = (p == 1) ? Bl : Bh;
        const uint32_t sa = smb + (c % NSTG) * STGB;
        const uint32_t sb = sa + OPB;
#pragma unroll
        for (int i = 0; i < 4; i++) {
            cp16(sa + swz(rowS[i], sgI[i]),
                 Asrc + (size_t)(m0 + rowS[i]) * DD + koff + sgI[i] * 8);
            cp16(sb + swz(rowS[i], sgI[i]),
                 Bsrc + (size_t)(n0 + rowS[i]) * DD + koff + sgI[i] * 8);
        }
        asm volatile("cp.async.commit_group;" ::: "memory");
    };

    const int a_row = lane & 15;
    const int aseg = (lane >> 4);                       // 0/1 (8-elem half)
    const int b_row = (lane & 7) + ((lane >> 4) << 3);
    const int bseg = (lane >> 3) & 1;

    load_chunk(0);
    load_chunk(1);

    for (int c = 0; c < NCHUNK; c++) {
        if (c + 2 < NCHUNK) {
            load_chunk(c + 2);
            asm volatile("cp.async.wait_group 2;" ::: "memory");
        } else if (c + 1 < NCHUNK) {
            asm volatile("cp.async.wait_group 1;" ::: "memory");
        } else {
            asm volatile("cp.async.wait_group 0;" ::: "memory");
        }
        __syncthreads();

        const uint32_t sa = smb + (c % NSTG) * STGB;
        const uint32_t sb = sa + OPB;

#pragma unroll
        for (int ks = 0; ks < 4; ks++) {
            uint32_t a[2][4];
#pragma unroll
            for (int mt = 0; mt < 2; mt++) {
                const int r = wm + mt * 16 + a_row;
                ldsm4(a[mt][0], a[mt][1], a[mt][2], a[mt][3],
                      sa + swz(r, 2 * ks + aseg));
            }
            uint32_t b[8][2];
#pragma unroll
            for (int np = 0; np < 4; np++) {
                const int r = wn + np * 16 + b_row;
                ldsm4(b[2 * np][0], b[2 * np][1], b[2 * np + 1][0], b[2 * np + 1][1],
                      sb + swz(r, 2 * ks + bseg));
            }
#pragma unroll
            for (int mt = 0; mt < 2; mt++)
#pragma unroll
                for (int nt = 0; nt < 8; nt++)
                    mma_bf16(acc[mt][nt], a[mt][0], a[mt][1], a[mt][2], a[mt][3],
                             b[nt][0], b[nt][1]);
        }
        __syncthreads();
    }

    const int erow = lane >> 2;
    const int ecol = (lane & 3) * 2;

    if (OMODE == 3) {
        // Transposed split epilogue via smem staging (64 n-rows x 128 m, pad 132).
        float* sT = (float*)dyn_smem;
        const int srow = tid >> 2;
        const int scol = (tid & 3) * 32;
#pragma unroll
        for (int hf = 0; hf < 2; hf++) {
            __syncthreads();
            if ((wid >> 2) == hf) {
#pragma unroll
                for (int mt = 0; mt < 2; mt++) {
                    const int m = wm + mt * 16 + erow;
#pragma unroll
                    for (int nt = 0; nt < 8; nt++) {
                        const int nl = nt * 8 + ecol;
                        sT[(nl + 0) * 132 + m] = acc[mt][nt][0];
                        sT[(nl + 1) * 132 + m] = acc[mt][nt][1];
                        sT[(nl + 0) * 132 + m + 8] = acc[mt][nt][2];
                        sT[(nl + 1) * 132 + m + 8] = acc[mt][nt][3];
                    }
                }
            }
            __syncthreads();
            const size_t n_glob = n0 + hf * 64 + srow;
            const float* sp = sT + srow * 132 + scol;
            __nv_bfloat16* dh = Ch + n_glob * MM + m0 + scol;
            __nv_bfloat16* dl = Cl + n_glob * MM + m0 + scol;
#pragma unroll
            for (int j = 0; j < 32; j += 2) {
                float f0 = sp[j], f1 = sp[j + 1];
                float h0 = __bfloat162float(__float2bfloat16(f0));
                float h1 = __bfloat162float(__float2bfloat16(f1));
                *(uint32_t*)(dh + j) = pack2(f0, f1);
                *(uint32_t*)(dl + j) = pack2(f0 - h0, f1 - h1);
            }
        }
        return;
    }

#pragma unroll
    for (int mt = 0; mt < 2; mt++) {
        const int row = m0 + wm + mt * 16 + erow;
#pragma unroll
        for (int nt = 0; nt < 8; nt++) {
            const int col = n0 + wn + nt * 8 + ecol;
            float v0 = acc[mt][nt][0], v1 = acc[mt][nt][1];
            float v2 = acc[mt][nt][2], v3 = acc[mt][nt][3];
            if (OMODE == 1) {
                v0 += bias[col]; v1 += bias[col + 1];
                v2 += bias[col]; v3 += bias[col + 1];
            }
            if (OMODE == 2) {
                float h0 = __bfloat162float(__float2bfloat16(v0));
                float h1 = __bfloat162float(__float2bfloat16(v1));
                float h2 = __bfloat162float(__float2bfloat16(v2));
                float h3 = __bfloat162float(__float2bfloat16(v3));
                *(uint32_t*)&Ch[(size_t)row * DD + col] = pack2(v0, v1);
                *(uint32_t*)&Cl[(size_t)row * DD + col] = pack2(v0 - h0, v1 - h1);
                *(uint32_t*)&Ch[(size_t)(row + 8) * DD + col] = pack2(v2, v3);
                *(uint32_t*)&Cl[(size_t)(row + 8) * DD + col] = pack2(v2 - h2, v3 - h3);
            } else {
                float2 p0; p0.x = v0; p0.y = v1;
                float2 p1; p1.x = v2; p1.y = v3;
                *(float2*)&C[(size_t)row * DD + col] = p0;
                *(float2*)&C[(size_t)(row + 8) * DD + col] = p1;
            }
        }
    }
}

// ---------------------------------------------------------------------------
// Prep kernels
// ---------------------------------------------------------------------------
__global__ __launch_bounds__(256)
void cvt_split_kernel(const float* __restrict__ in, __nv_bfloat16* __restrict__ hi,
                      __nv_bfloat16* __restrict__ lo, int n4) {
    int i = blockIdx.x * blockDim.x + threadIdx.x;
    if (i >= n4) return;
    float4 v = ((const float4*)in)[i];
    float h0 = __bfloat162float(__float2bfloat16(v.x));
    float h1 = __bfloat162float(__float2bfloat16(v.y));
    float h2 = __bfloat162float(__float2bfloat16(v.z));
    float h3 = __bfloat162float(__float2bfloat16(v.w));
    ((uint32_t*)hi)[2 * i + 0] = pack2(v.x, v.y);
    ((uint32_t*)hi)[2 * i + 1] = pack2(v.z, v.w);
    ((uint32_t*)lo)[2 * i + 0] = pack2(v.x - h0, v.y - h1);
    ((uint32_t*)lo)[2 * i + 1] = pack2(v.z - h2, v.w - h3);
}

__global__ __launch_bounds__(256)
void wsplit_t_kernel(const float* __restrict__ W, __nv_bfloat16* __restrict__ Th,
                     __nv_bfloat16* __restrict__ Tl) {
    __shared__ float t[32][33];
    const int bx = blockIdx.x * 32;
    const int by = blockIdx.y * 32;
    const int x = bx + threadIdx.x;
#pragma unroll
    for (int j = threadIdx.y; j < 32; j += 8)
        t[j][threadIdx.x] = W[(size_t)(by + j) * DD + x];
    __syncthreads();
    const int xo = by + threadIdx.x;
#pragma unroll
    for (int j = threadIdx.y; j < 32; j += 8) {
        float v = t[threadIdx.x][j];
        __nv_bfloat16 h = __float2bfloat16(v);
        Th[(size_t)(bx + j) * DD + xo] = h;
        Tl[(size_t)(bx + j) * DD + xo] = __float2bfloat16(v - __bfloat162float(h));
    }
}

// ---------------------------------------------------------------------------
// HMMA flash-attention, bf16 split precision, SW128-swizzled smem (96KB ->
// 2 CTA/SM). Q tile 128, K/V tiles 64, double-buffered cp.async.
// ---------------------------------------------------------------------------
#define QTB 16384                     // Q tile bytes (128 x 128B)
#define KVTB 8192                     // K/V tile bytes (64 x 128B)
#define KVSTGB (4 * KVTB)             // 32768 per stage
#define ATTN_SMEM_B (2 * QTB + 2 * KVSTGB)   // 98304 B

__global__ __launch_bounds__(256, 2)
void attn_mma(const __nv_bfloat16* __restrict__ qh, const __nv_bfloat16* __restrict__ ql,
              const __nv_bfloat16* __restrict__ kh, const __nv_bfloat16* __restrict__ kl,
              const __nv_bfloat16* __restrict__ vth, const __nv_bfloat16* __restrict__ vtl,
              __nv_bfloat16* __restrict__ ch, __nv_bfloat16* __restrict__ cl) {
    extern __shared__ __align__(16) char attn_smem[];
    const uint32_t smb = smem_u32(attn_smem);

    const int tid = threadIdx.x;
    const int wid = tid >> 5;
    const int lane = tid & 31;
    const int qt = blockIdx.x;
    const int h = blockIdx.y;
    const int b = blockIdx.z;
    const int q0 = qt * 128;
    const int wm = wid * 16;
    const int g = lane >> 2;
    const int t_ = lane & 3;

    const size_t rowQ = (size_t)b * SS + q0;

    const int a_row = lane & 15;
    const int aseg = (lane >> 4);
    const int b_row = (lane & 7) + ((lane >> 4) << 3);
    const int bseg = (lane >> 3) & 1;

    // ---- load Q (hi+lo): 2048 segs of 16B, 8 per thread ----
#pragma unroll
    for (int i = 0; i < 8; i++) {
        int gi = tid + 256 * i;
        int tile = gi >> 10;            // 0=Qh, 1=Ql
        int gg = gi & 1023;
        int row = gg >> 3, sg = gg & 7;
        const __nv_bfloat16* src = (tile ? ql : qh) + (rowQ + row) * DD + h * HDIM + sg * 8;
        cp16(smb + tile * QTB + swz(row, sg), src);
    }

    auto load_kv = [&](int t, int s) {
        const size_t rowK = (size_t)b * SS + t * 64;
        const uint32_t base = smb + 2 * QTB + s * KVSTGB;
#pragma unroll
        for (int i = 0; i < 8; i++) {
            int gi = tid + 256 * i;
            int tile = gi >> 9;         // 0=Kh 1=Kl 2=Vth 3=Vtl
            int gg = gi & 511;
            int row = gg >> 3, sg = gg & 7;
            const __nv_bfloat16* src;
            if (tile == 0)      src = kh + (rowK + row) * DD + h * HDIM + sg * 8;
            else if (tile == 1) src = kl + (rowK + row) * DD + h * HDIM + sg * 8;
            else if (tile == 2) src = vth + (size_t)(h * HDIM + row) * MM + rowK + sg * 8;
            else                src = vtl + (size_t)(h * HDIM + row) * MM + rowK + sg * 8;
            cp16(base + tile * KVTB + swz(row, sg), src);
        }
        asm volatile("cp.async.commit_group;" ::: "memory");
    };

    const int ktiles = min(2 * qt + 3, SS / 64);

    load_kv(0, 0);

    float oacc[8][4];
    float m0 = -1e30f, m1 = -1e30f, l0 = 0.f, l1 = 0.f;
#pragma unroll
    for (int nt = 0; nt < 8; nt++)
#pragma unroll
        for (int e = 0; e < 4; e++) oacc[nt][e] = 0.f;

    for (int t = 0; t < ktiles; t++) {
        if (t + 1 < ktiles) {
            load_kv(t + 1, (t + 1) & 1);
            asm volatile("cp.async.wait_group 1;" ::: "memory");
        } else {
            asm volatile("cp.async.wait_group 0;" ::: "memory");
        }
        __syncthreads();

        const int s = t & 1;
        const int k0 = t * 64;
        // Pure-lookahead tile: only warp 7 (query row q0+127) has unmasked work.
        const bool skip = (k0 > q0 + 127) && (wid != 7);

        if (!skip) {
            const uint32_t sQh = smb;
            const uint32_t sQl = smb + QTB;
            const uint32_t sKh = smb + 2 * QTB + s * KVSTGB;
            const uint32_t sKl = sKh + KVTB;
            const uint32_t sVh = sKh + 2 * KVTB;
            const uint32_t sVl = sKh + 3 * KVTB;

            float sacc[8][4];
#pragma unroll
            for (int nt = 0; nt < 8; nt++)
#pragma unroll
                for (int e = 0; e < 4; e++) sacc[nt][e] = 0.f;

#pragma unroll
            for (int pass = 0; pass < 3; pass++) {
                const uint32_t A = (pass < 2) ? sQh : sQl;
                const uint32_t Bk = (pass == 1) ? sKl : sKh;
#pragma unroll
                for (int ks = 0; ks < 4; ks++) {
                    uint32_t a0, a1, a2, a3;
                    ldsm4(a0, a1, a2, a3, A + swz(wm + a_row, 2 * ks + aseg));
#pragma unroll
                    for (int np = 0; np < 4; np++) {
                        uint32_t b0, b1, b2, b3;
                        ldsm4(b0, b1, b2, b3, Bk + swz(np * 16 + b_row, 2 * ks + bseg));
                        mma_bf16(sacc[2 * np], a0, a1, a2, a3, b0, b1);
                        mma_bf16(sacc[2 * np + 1], a0, a1, a2, a3, b2, b3);
                    }
                }
            }

#pragma unroll
            for (int nt = 0; nt < 8; nt++)
#pragma unroll
                for (int e = 0; e < 4; e++) sacc[nt][e] *= 0.125f;

            const int qr0 = q0 + wm + g;
            if (k0 >= q0) {
#pragma unroll
                for (int nt = 0; nt < 8; nt++) {
                    const int c = k0 + nt * 8 + 2 * t_;
                    if (c     > qr0 + 1) sacc[nt][0] = -1e30f;
                    if (c + 1 > qr0 + 1) sacc[nt][1] = -1e30f;
                    if (c     > qr0 + 9) sacc[nt][2] = -1e30f;
                    if (c + 1 > qr0 + 9) sacc[nt][3] = -1e30f;
                }
            }

            float mx0 = -1e30f, mx1 = -1e30f;
#pragma unroll
            for (int nt = 0; nt < 8; nt++) {
                mx0 = fmaxf(mx0, fmaxf(sacc[nt][0], sacc[nt][1]));
                mx1 = fmaxf(mx1, fmaxf(sacc[nt][2], sacc[nt][3]));
            }
            mx0 = fmaxf(mx0, __shfl_xor_sync(0xffffffffu, mx0, 1));
            mx0 = fmaxf(mx0, __shfl_xor_sync(0xffffffffu, mx0, 2));
            mx1 = fmaxf(mx1, __shfl_xor_sync(0xffffffffu, mx1, 1));
            mx1 = fmaxf(mx1, __shfl_xor_sync(0xffffffffu, mx1, 2));

            const float mn0 = fmaxf(m0, mx0), mn1 = fmaxf(m1, mx1);
            const float cor0 = __expf(m0 - mn0), cor1 = __expf(m1 - mn1);
            m0 = mn0; m1 = mn1;

            float rs0 = 0.f, rs1 = 0.f;
#pragma unroll
            for (int nt = 0; nt < 8; nt++) {
                sacc[nt][0] = __expf(sacc[nt][0] - mn0); rs0 += sacc[nt][0];
                sacc[nt][1] = __expf(sacc[nt][1] - mn0); rs0 += sacc[nt][1];
                sacc[nt][2] = __expf(sacc[nt][2] - mn1); rs1 += sacc[nt][2];
                sacc[nt][3] = __expf(sacc[nt][3] - mn1); rs1 += sacc[nt][3];
            }
            rs0 += __shfl_xor_sync(0xffffffffu, rs0, 1);
            rs0 += __shfl_xor_sync(0xffffffffu, rs0, 2);
            rs1 += __shfl_xor_sync(0xffffffffu, rs1, 1);
            rs1 += __shfl_xor_sync(0xffffffffu, rs1, 2);
            l0 = l0 * cor0 + rs0;
            l1 = l1 * cor1 + rs1;

#pragma unroll
            for (int nt = 0; nt < 8; nt++) {
                oacc[nt][0] *= cor0; oacc[nt][1] *= cor0;
                oacc[nt][2] *= cor1; oacc[nt][3] *= cor1;
            }

#pragma unroll
            for (int ks = 0; ks < 4; ks++) {
                const float* P0 = sacc[2 * ks];
                const float* P1 = sacc[2 * ks + 1];
                float h00 = __bfloat162float(__float2bfloat16(P0[0]));
                float h01 = __bfloat162float(__float2bfloat16(P0[1]));
                float h02 = __bfloat162float(__float2bfloat16(P0[2]));
                float h03 = __bfloat162float(__float2bfloat16(P0[3]));
                float h10 = __bfloat162float(__float2bfloat16(P1[0]));
                float h11 = __bfloat162float(__float2bfloat16(P1[1]));
                float h12 = __bfloat162float(__float2bfloat16(P1[2]));
                float h13 = __bfloat162float(__float2bfloat16(P1[3]));
                uint32_t ah0 = pack2(P0[0], P0[1]);
                uint32_t ah1 = pack2(P0[2], P0[3]);
                uint32_t ah2 = pack2(P1[0], P1[1]);
                uint32_t ah3 = pack2(P1[2], P1[3]);
                uint32_t al0 = pack2(P0[0] - h00, P0[1] - h01);
                uint32_t al1 = pack2(P0[2] - h02, P0[3] - h03);
                uint32_t al2 = pack2(P1[0] - h10, P1[1] - h11);
                uint32_t al3 = pack2(P1[2] - h12, P1[3] - h13);

#pragma unroll
                for (int np = 0; np < 4; np++) {
                    uint32_t bh0, bh1, bh2, bh3, bl0, bl1, bl2, bl3;
                    ldsm4(bh0, bh1, bh2, bh3, sVh + swz(np * 16 + b_row, 2 * ks + bseg));
                    ldsm4(bl0, bl1, bl2, bl3, sVl + swz(np * 16 + b_row, 2 * ks + bseg));
                    mma_bf16(oacc[2 * np],     ah0, ah1, ah2, ah3, bh0, bh1);
                    mma_bf16(oacc[2 * np + 1], ah0, ah1, ah2, ah3, bh2, bh3);
                    mma_bf16(oacc[2 * np],     ah0, ah1, ah2, ah3, bl0, bl1);
                    mma_bf16(oacc[2 * np + 1], ah0, ah1, ah2, ah3, bl2, bl3);
                    mma_bf16(oacc[2 * np],     al0, al1, al2, al3, bh0, bh1);
                    mma_bf16(oacc[2 * np + 1], al0, al1, al2, al3, bh2, bh3);
                }
            }
        }
        __syncthreads();
    }

    const float il0 = 1.0f / l0, il1 = 1.0f / l1;
    const size_t r0g = (size_t)b * SS + q0 + wm + g;
    const size_t r1g = r0g + 8;
#pragma unroll
    for (int nt = 0; nt < 8; nt++) {
        const int col = h * HDIM + nt * 8 + 2 * t_;
        float f0 = oacc[nt][0] * il0, f1 = oacc[nt][1] * il0;
        float f2 = oacc[nt][2] * il1, f3 = oacc[nt][3] * il1;
        float e0 = __bfloat162float(__float2bfloat16(f0));
        float e1 = __bfloat162float(__float2bfloat16(f1));
        float e2 = __bfloat162float(__float2bfloat16(f2));
        float e3 = __bfloat162float(__float2bfloat16(f3));
        *(uint32_t*)&ch[r0g * DD + col] = pack2(f0, f1);
        *(uint32_t*)&cl[r0g * DD + col] = pack2(f0 - e0, f1 - e1);
        *(uint32_t*)&ch[r1g * DD + col] = pack2(f2, f3);
        *(uint32_t*)&cl[r1g * DD + col] = pack2(f2 - e2, f3 - e3);
    }
}

// ---------------------------------------------------------------------------
// kernel_launch
// ---------------------------------------------------------------------------
extern "C" void kernel_launch(void* const* d_in, const int* in_sizes, int n_in,
                              void* d_out, int out_size) {
    (void)in_sizes; (void)n_in; (void)out_size;
    const float* x  = (const float*)d_in[0];
    const float* Wq = (const float*)d_in[1];
    const float* Wk = (const float*)d_in[2];
    const float* Wv = (const float*)d_in[3];
    const float* Wo = (const float*)d_in[4];
    const float* bo = (const float*)d_in[5];
    float* out = (float*)d_out;

    __nv_bfloat16 *xh, *xl, *qh, *ql, *kh, *kl, *vth, *vtl, *ch, *cl, *wh, *wl;
    cudaGetSymbolAddress((void**)&xh, g_xh);
    cudaGetSymbolAddress((void**)&xl, g_xl);
    cudaGetSymbolAddress((void**)&qh, g_qh);
    cudaGetSymbolAddress((void**)&ql, g_ql);
    cudaGetSymbolAddress((void**)&kh, g_kh);
    cudaGetSymbolAddress((void**)&kl, g_kl);
    cudaGetSymbolAddress((void**)&vth, g_vth);
    cudaGetSymbolAddress((void**)&vtl, g_vtl);
    cudaGetSymbolAddress((void**)&ch, g_ch);
    cudaGetSymbolAddress((void**)&cl, g_cl);
    cudaGetSymbolAddress((void**)&wh, g_wh);
    cudaGetSymbolAddress((void**)&wl, g_wl);

    cudaFuncSetAttribute(attn_mma, cudaFuncAttributeMaxDynamicSharedMemorySize, ATTN_SMEM_B);
    cudaFuncSetAttribute(gemm_mma<1>, cudaFuncAttributeMaxDynamicSharedMemorySize, GEMM_SMEM);
    cudaFuncSetAttribute(gemm_mma<2>, cudaFuncAttributeMaxDynamicSharedMemorySize, GEMM_SMEM);
    cudaFuncSetAttribute(gemm_mma<3>, cudaFuncAttributeMaxDynamicSharedMemorySize, GEMM_SMEM);

    // Prep
    const int n4 = MM * DD / 4;
    cvt_split_kernel<<<(n4 + 255) / 256, 256>>>(x, xh, xl, n4);
    dim3 tgrid(DD / 32, DD / 32), tblk(32, 8);
    wsplit_t_kernel<<<tgrid, tblk>>>(Wq, wh + 0 * DD * DD, wl + 0 * DD * DD);
    wsplit_t_kernel<<<tgrid, tblk>>>(Wk, wh + 1 * DD * DD, wl + 1 * DD * DD);
    wsplit_t_kernel<<<tgrid, tblk>>>(Wv, wh + 2 * DD * DD, wl + 2 * DD * DD);
    wsplit_t_kernel<<<tgrid, tblk>>>(Wo, wh + 3 * DD * DD, wl + 3 * DD * DD);

    // Projections (Q,K -> split bf16; V -> transposed split bf16, fused)
    dim3 ggrid(DD / 128, MM / 128);
    gemm_mma<2><<<ggrid, 256, GEMM_SMEM>>>(xh, xl, wh + 0 * DD * DD, wl + 0 * DD * DD,
                                           nullptr, nullptr, qh, ql);
    gemm_mma<2><<<ggrid, 256, GEMM_SMEM>>>(xh, xl, wh + 1 * DD * DD, wl + 1 * DD * DD,
                                           nullptr, nullptr, kh, kl);
    gemm_mma<3><<<ggrid, 256, GEMM_SMEM>>>(xh, xl, wh + 2 * DD * DD, wl + 2 * DD * DD,
                                           nullptr, nullptr, vth, vtl);

    // Attention (HMMA split)
    dim3 agrid(SS / 128, HH, BB);
    attn_mma<<<agrid, 256, ATTN_SMEM_B>>>(qh, ql, kh, kl, vth, vtl, ch, cl);

    // Output projection (+bias)
    gemm_mma<1><<<ggrid, 256, GEMM_SMEM>>>(ch, cl, wh + 3 * DD * DD, wl + 3 * DD * DD,
                                           bo, out, nullptr, nullptr);
}